// round 12
// baseline (speedup 1.0000x reference)
#include <cuda_runtime.h>
#include <cuda_bf16.h>
#include <cuda_fp16.h>
#include <cstdint>

// ---------------- problem constants ----------------
#define NN 20000
#define EE 200000
#define DIM 256
#define HEADS 4
#define DH 64
#define INNER 256
#define EDIM 512
#define FF 1024
#define OUTD 128
#define DEPTH 2
#define LNEPS 1e-5f

// ---------------- scratch (device globals; no allocation allowed) ----------------
__device__ float g_x[NN * DIM];
__device__ __half g_xnh[NN * DIM];                    // LN output, fp16
__device__ __half g_qkvh[NN * 3 * INNER];             // [q | k | v] fp16 (30.7 MB)
__device__ __half g_eah[(size_t)EE * EDIM];           // fp16 edge_attr (204.8 MB)
__device__ __nv_bfloat16 g_e[(size_t)EE * INNER];     // bf16 edge projections
__device__ float g_p[EE * HEADS];
__device__ float g_den[NN * HEADS];
__device__ float g_agg[NN * INNER];
__device__ float g_y[NN * DIM];
__device__ __half g_ffh[NN * FF];                     // GELU out, fp16
__device__ float g_bqkv[DEPTH * 3 * INNER];
// tf32 weights (wo, proj)
#define WQKV_OFF  0
#define WE_OFF    393216
#define WO_OFF    655360
#define WF1_OFF   786432
#define WF2_OFF   1310720
#define WPROJ_OFF 1835008
#define WT_TOTAL  1867776
__device__ float g_wt[WT_TOTAL];
// fp16 weights (qkv, we, ff1, ff2)
#define WTH_TOTAL 1703936
__device__ __half g_wth[WTH_TOTAL];

// ---------------- helpers ----------------
__device__ __forceinline__ uint32_t f2tf32(float f)
{
    uint32_t r;
    asm("cvt.rna.tf32.f32 %0, %1;" : "=r"(r) : "f"(f));
    return r;
}

__device__ __forceinline__ void mma_tf32(float* c, const uint32_t* a, const uint32_t* b)
{
    asm volatile(
        "mma.sync.aligned.m16n8k8.row.col.f32.tf32.tf32.f32 "
        "{%0,%1,%2,%3}, {%4,%5,%6,%7}, {%8,%9}, {%0,%1,%2,%3};"
        : "+f"(c[0]), "+f"(c[1]), "+f"(c[2]), "+f"(c[3])
        : "r"(a[0]), "r"(a[1]), "r"(a[2]), "r"(a[3]), "r"(b[0]), "r"(b[1]));
}

__device__ __forceinline__ void mma_f16(float* c, const uint32_t* a, const uint32_t* b)
{
    asm volatile(
        "mma.sync.aligned.m16n8k16.row.col.f32.f16.f16.f32 "
        "{%0,%1,%2,%3}, {%4,%5,%6,%7}, {%8,%9}, {%0,%1,%2,%3};"
        : "+f"(c[0]), "+f"(c[1]), "+f"(c[2]), "+f"(c[3])
        : "r"(a[0]), "r"(a[1]), "r"(a[2]), "r"(a[3]), "r"(b[0]), "r"(b[1]));
}

__device__ __forceinline__ uint32_t smem_u32(const void* p)
{
    return (uint32_t)__cvta_generic_to_shared(p);
}

__device__ __forceinline__ float2 bf2f2(uint32_t u)
{
    __nv_bfloat162 h = *reinterpret_cast<__nv_bfloat162*>(&u);
    return __bfloat1622float2(h);
}

__device__ __forceinline__ float2 h2f2(uint32_t u)
{
    __half2 h = *reinterpret_cast<__half2*>(&u);
    return __half22float2(h);
}

__device__ __forceinline__ float gelu_f(float v)
{
    float c3 = v * v * v;
    return 0.5f * v * (1.f + tanhf(0.7978845608028654f * (v + 0.044715f * c3)));
}

// ---------------- TF32 GEMM v4 (wo + proj; unchanged) ----------------
#define AS_STRIDE 36
#define BS_STRIDE 136
#define STAGE_WORDS (128 * AS_STRIDE + 32 * BS_STRIDE)
#define SMEM_WORDS (3 * STAGE_WORDS)
#define SMEM_BYTES (SMEM_WORDS * 4)

__global__ __launch_bounds__(128, 2) void tgemm_v4(
    const float* __restrict__ A, const float* __restrict__ B,
    const float* __restrict__ bias, float* __restrict__ C,
    int M, int N, int K)
{
    extern __shared__ uint32_t smem[];
    const int tid = threadIdx.x;
    const int warp = tid >> 5, lane = tid & 31;
    const int warpM = warp >> 1, warpN = warp & 1;
    const int g = lane >> 2, tg = lane & 3;
    const int row0 = blockIdx.y * 128, col0 = blockIdx.x * 128;
    const int lm_row = (lane & 7) + ((lane >> 3) & 1) * 8;
    const int lm_col = (lane >> 4) * 4;

    float acc[4][8][4];
#pragma unroll
    for (int i = 0; i < 4; i++)
#pragma unroll
        for (int j = 0; j < 8; j++)
#pragma unroll
            for (int r = 0; r < 4; r++) acc[i][j][r] = 0.f;

    auto stage = [&](int buf, int k0) {
        uint32_t* As = smem + (size_t)buf * STAGE_WORDS;
        uint32_t* Bs = As + 128 * AS_STRIDE;
#pragma unroll
        for (int i = 0; i < 8; i++) {
            int c = tid + 128 * i;
            int r = c >> 3, cc = (c & 7) * 4;
            int grow = row0 + r;
            int sz = (grow < M) ? 16 : 0;
            if (grow >= M) grow = M - 1;
            const float* src = A + (size_t)grow * K + k0 + cc;
            uint32_t dstp = smem_u32(&As[r * AS_STRIDE + cc]);
            asm volatile("cp.async.cg.shared.global [%0], [%1], 16, %2;"
                         :: "r"(dstp), "l"(src), "r"(sz));
        }
#pragma unroll
        for (int i = 0; i < 8; i++) {
            int c = tid + 128 * i;
            int r = c >> 5, cc = (c & 31) * 4;
            const float* src = B + (size_t)(k0 + r) * N + col0 + cc;
            uint32_t dstp = smem_u32(&Bs[r * BS_STRIDE + cc]);
            asm volatile("cp.async.cg.shared.global [%0], [%1], 16, 16;"
                         :: "r"(dstp), "l"(src));
        }
        asm volatile("cp.async.commit_group;");
    };

    const int nk = K >> 5;
    stage(0, 0);
    stage(1, 32);

    int buf = 0;
    for (int t = 0; t < nk; t++) {
        if (t + 2 < nk) stage((t + 2) % 3, (t + 2) * 32);
        int rem = nk - 1 - t;
        if (rem >= 2)      asm volatile("cp.async.wait_group 2;");
        else if (rem == 1) asm volatile("cp.async.wait_group 1;");
        else               asm volatile("cp.async.wait_group 0;");
        __syncthreads();

        const uint32_t* Ab = smem + (size_t)buf * STAGE_WORDS;
        const uint32_t* Bb = Ab + 128 * AS_STRIDE;

#pragma unroll
        for (int ks = 0; ks < 4; ks++) {
            const int kk = ks * 8;
            uint32_t a[4][4], b[8][2];
#pragma unroll
            for (int mf = 0; mf < 4; mf++) {
                int m0 = warpM * 64 + mf * 16;
                uint32_t addr = smem_u32(&Ab[(m0 + lm_row) * AS_STRIDE + kk + lm_col]);
                asm volatile("ldmatrix.sync.aligned.m8n8.x4.shared.b16 {%0,%1,%2,%3}, [%4];"
                             : "=r"(a[mf][0]), "=r"(a[mf][1]), "=r"(a[mf][2]), "=r"(a[mf][3])
                             : "r"(addr));
            }
#pragma unroll
            for (int nf = 0; nf < 8; nf++) {
                int n = warpN * 64 + nf * 8 + g;
                b[nf][0] = Bb[(kk + tg) * BS_STRIDE + n];
                b[nf][1] = Bb[(kk + tg + 4) * BS_STRIDE + n];
            }
#pragma unroll
            for (int mf = 0; mf < 4; mf++)
#pragma unroll
                for (int nf = 0; nf < 8; nf++)
                    mma_tf32(acc[mf][nf], a[mf], b[nf]);
        }
        __syncthreads();
        buf = (buf + 1) % 3;
    }

#pragma unroll
    for (int mf = 0; mf < 4; mf++) {
#pragma unroll
        for (int half = 0; half < 2; half++) {
            int row = row0 + warpM * 64 + mf * 16 + g + half * 8;
            if (row >= M) continue;
#pragma unroll
            for (int nf = 0; nf < 8; nf++) {
                int col = col0 + warpN * 64 + nf * 8 + 2 * tg;
                float v0 = acc[mf][nf][half * 2 + 0] + bias[col];
                float v1 = acc[mf][nf][half * 2 + 1] + bias[col + 1];
                *reinterpret_cast<float2*>(C + (size_t)row * N + col) = make_float2(v0, v1);
            }
        }
    }
}

// ---------------- FP16 GEMM v2: 256 threads, 8 warps (2x4), warp tile 64x32 ----------------
// EPI: 0 = bias -> fp32; 1 = bias+GELU -> fp16; 2 = bias -> bf16; 3 = bias -> fp16
#define HA_STRIDE 40
#define HB_STRIDE 136
#define HSTAGE (128 * HA_STRIDE + 32 * HB_STRIDE)
#define HSMEM_BYTES (3 * HSTAGE * 2)

template <int EPI>
__global__ __launch_bounds__(256, 2) void tgemm_h16(
    const __half* __restrict__ A, const __half* __restrict__ B,
    const float* __restrict__ bias, void* __restrict__ C,
    int M, int N, int K)
{
    extern __shared__ __half hsmem[];
    const int tid = threadIdx.x;
    const int warp = tid >> 5, lane = tid & 31;
    const int warpM = warp >> 2, warpN = warp & 3;
    const int g = lane >> 2, tg = lane & 3;
    const int row0 = blockIdx.y * 128, col0 = blockIdx.x * 128;
    const int lm_row = (lane & 7) + ((lane >> 3) & 1) * 8;
    const int lm_col = (lane >> 4) * 8;

    float acc[4][4][4];
#pragma unroll
    for (int i = 0; i < 4; i++)
#pragma unroll
        for (int j = 0; j < 4; j++)
#pragma unroll
            for (int r = 0; r < 4; r++) acc[i][j][r] = 0.f;

    auto stage = [&](int buf, int k0) {
        __half* As = hsmem + (size_t)buf * HSTAGE;
        __half* Bs = As + 128 * HA_STRIDE;
        // A tile 128x32 fp16: 512 16B-chunks, 2/thread
#pragma unroll
        for (int i = 0; i < 2; i++) {
            int c = tid + 256 * i;
            int r = c >> 2, cc = (c & 3) * 8;
            int grow = row0 + r;
            int sz = (grow < M) ? 16 : 0;
            if (grow >= M) grow = M - 1;
            const __half* src = A + (size_t)grow * K + k0 + cc;
            uint32_t dstp = smem_u32(&As[r * HA_STRIDE + cc]);
            asm volatile("cp.async.cg.shared.global [%0], [%1], 16, %2;"
                         :: "r"(dstp), "l"(src), "r"(sz));
        }
        // B tile 32x128 fp16: 512 16B-chunks, 2/thread
#pragma unroll
        for (int i = 0; i < 2; i++) {
            int c = tid + 256 * i;
            int r = c >> 4, cc = (c & 15) * 8;
            const __half* src = B + (size_t)(k0 + r) * N + col0 + cc;
            uint32_t dstp = smem_u32(&Bs[r * HB_STRIDE + cc]);
            asm volatile("cp.async.cg.shared.global [%0], [%1], 16, 16;"
                         :: "r"(dstp), "l"(src));
        }
        asm volatile("cp.async.commit_group;");
    };

    const int nk = K >> 5;
    stage(0, 0);
    stage(1, 32);

    int buf = 0;
    for (int t = 0; t < nk; t++) {
        if (t + 2 < nk) stage((t + 2) % 3, (t + 2) * 32);
        int rem = nk - 1 - t;
        if (rem >= 2)      asm volatile("cp.async.wait_group 2;");
        else if (rem == 1) asm volatile("cp.async.wait_group 1;");
        else               asm volatile("cp.async.wait_group 0;");
        __syncthreads();

        const __half* Ab = hsmem + (size_t)buf * HSTAGE;
        const __half* Bb = Ab + 128 * HA_STRIDE;

#pragma unroll
        for (int ks = 0; ks < 2; ks++) {
            const int kk = ks * 16;
            uint32_t a[4][4], b[4][2];
#pragma unroll
            for (int mf = 0; mf < 4; mf++) {
                int m0 = warpM * 64 + mf * 16;
                uint32_t addr = smem_u32(&Ab[(m0 + lm_row) * HA_STRIDE + kk + lm_col]);
                asm volatile("ldmatrix.sync.aligned.m8n8.x4.shared.b16 {%0,%1,%2,%3}, [%4];"
                             : "=r"(a[mf][0]), "=r"(a[mf][1]), "=r"(a[mf][2]), "=r"(a[mf][3])
                             : "r"(addr));
            }
#pragma unroll
            for (int nf2 = 0; nf2 < 2; nf2++) {
                int n0 = warpN * 32 + nf2 * 16;
                int brow = kk + (lane & 7) + ((lane >> 3) & 1) * 8;
                int bcol = n0 + (lane >> 4) * 8;
                uint32_t addr = smem_u32(&Bb[brow * HB_STRIDE + bcol]);
                asm volatile("ldmatrix.sync.aligned.m8n8.x4.trans.shared.b16 {%0,%1,%2,%3}, [%4];"
                             : "=r"(b[2 * nf2][0]), "=r"(b[2 * nf2][1]),
                               "=r"(b[2 * nf2 + 1][0]), "=r"(b[2 * nf2 + 1][1])
                             : "r"(addr));
            }
#pragma unroll
            for (int mf = 0; mf < 4; mf++)
#pragma unroll
                for (int nf = 0; nf < 4; nf++)
                    mma_f16(acc[mf][nf], a[mf], b[nf]);
        }
        __syncthreads();
        buf = (buf + 1) % 3;
    }

#pragma unroll
    for (int mf = 0; mf < 4; mf++) {
#pragma unroll
        for (int half = 0; half < 2; half++) {
            int row = row0 + warpM * 64 + mf * 16 + g + half * 8;
            if (row >= M) continue;
#pragma unroll
            for (int nf = 0; nf < 4; nf++) {
                int col = col0 + warpN * 32 + nf * 8 + 2 * tg;
                float v0 = acc[mf][nf][half * 2 + 0] + bias[col];
                float v1 = acc[mf][nf][half * 2 + 1] + bias[col + 1];
                if (EPI == 0) {
                    *reinterpret_cast<float2*>(
                        reinterpret_cast<float*>(C) + (size_t)row * N + col) = make_float2(v0, v1);
                } else if (EPI == 1) {
                    v0 = gelu_f(v0);
                    v1 = gelu_f(v1);
                    __half2 h = __floats2half2_rn(v0, v1);
                    *reinterpret_cast<__half2*>(
                        reinterpret_cast<__half*>(C) + (size_t)row * N + col) = h;
                } else if (EPI == 2) {
                    __nv_bfloat162 h = __floats2bfloat162_rn(v0, v1);
                    *reinterpret_cast<__nv_bfloat162*>(
                        reinterpret_cast<__nv_bfloat16*>(C) + (size_t)row * N + col) = h;
                } else {
                    __half2 h = __floats2half2_rn(v0, v1);
                    *reinterpret_cast<__half2*>(
                        reinterpret_cast<__half*>(C) + (size_t)row * N + col) = h;
                }
            }
        }
    }
}

// ---------------- edge_attr fp32 -> fp16 ----------------
__global__ void cvt_ea_k(const float* __restrict__ in, __half* __restrict__ out)
{
    size_t i = (size_t)blockIdx.x * blockDim.x + threadIdx.x;
    size_t n8 = (size_t)EE * EDIM / 8;
    if (i >= n8) return;
    const float4* p = reinterpret_cast<const float4*>(in) + i * 2;
    float4 v0 = p[0], v1 = p[1];
    __half2 h0 = __floats2half2_rn(v0.x, v0.y);
    __half2 h1 = __floats2half2_rn(v0.z, v0.w);
    __half2 h2 = __floats2half2_rn(v1.x, v1.y);
    __half2 h3 = __floats2half2_rn(v1.z, v1.w);
    uint4 u;
    u.x = *reinterpret_cast<uint32_t*>(&h0);
    u.y = *reinterpret_cast<uint32_t*>(&h1);
    u.z = *reinterpret_cast<uint32_t*>(&h2);
    u.w = *reinterpret_cast<uint32_t*>(&h3);
    reinterpret_cast<uint4*>(out)[i] = u;
}

// ---------------- fused weight conversion + bias concat ----------------
__global__ void cvt_all_k(const float* __restrict__ Wq, const float* __restrict__ Wkv,
                          const float* __restrict__ We, const float* __restrict__ Wo,
                          const float* __restrict__ Wf1, const float* __restrict__ Wf2,
                          const float* __restrict__ Wp, float* __restrict__ out,
                          __half* __restrict__ outh,
                          const float* __restrict__ bq, const float* __restrict__ bkv,
                          float* __restrict__ bqkv)
{
    int i = blockIdx.x * blockDim.x + threadIdx.x;
    if (i < DEPTH * 3 * INNER) {
        int d = i / (3 * INNER), c = i % (3 * INNER);
        bqkv[i] = (c < INNER) ? bq[d * INNER + c] : bkv[d * 2 * INNER + (c - INNER)];
    }
    if (i >= WT_TOTAL) return;
    float v;
    if (i < WE_OFF) {
        int t = i;
        int d = t / (DIM * 3 * INNER);
        int r = (t / (3 * INNER)) % DIM;
        int c = t % (3 * INNER);
        v = (c < INNER) ? Wq[((size_t)d * DIM + r) * INNER + c]
                        : Wkv[((size_t)d * DIM + r) * (2 * INNER) + (c - INNER)];
    } else if (i < WO_OFF) v = We[i - WE_OFF];
    else if (i < WF1_OFF) v = Wo[i - WO_OFF];
    else if (i < WF2_OFF) v = Wf1[i - WF1_OFF];
    else if (i < WPROJ_OFF) v = Wf2[i - WF2_OFF];
    else v = Wp[i - WPROJ_OFF];
    out[i] = __uint_as_float(f2tf32(v));
    if (i < WO_OFF) outh[i] = __float2half_rn(v);
    else if (i >= WF1_OFF && i < WPROJ_OFF) outh[i - 131072] = __float2half_rn(v);
}

// ---------------- LayerNorm (fp16 out; first use only) ----------------
__global__ void layernorm_k(const float* __restrict__ x, const float* __restrict__ g,
                            const float* __restrict__ b, __half* __restrict__ out, int n)
{
    int w = (blockIdx.x * blockDim.x + threadIdx.x) >> 5;
    int lane = threadIdx.x & 31;
    if (w >= n) return;
    const float* xp = x + (size_t)w * DIM;
    float v[8], s = 0.f, sq = 0.f;
#pragma unroll
    for (int j = 0; j < 8; j++) {
        v[j] = xp[lane + j * 32];
        s += v[j];
        sq += v[j] * v[j];
    }
#pragma unroll
    for (int o = 16; o; o >>= 1) {
        s += __shfl_xor_sync(0xffffffffu, s, o);
        sq += __shfl_xor_sync(0xffffffffu, sq, o);
    }
    float mean = s * (1.f / DIM);
    float var = sq * (1.f / DIM) - mean * mean;
    float rstd = rsqrtf(var + LNEPS);
#pragma unroll
    for (int j = 0; j < 8; j++) {
        int d = lane + j * 32;
        out[(size_t)w * DIM + d] = __float2half_rn((v[j] - mean) * rstd * g[d] + b[d]);
    }
}

// ---------------- fused gated residual + LayerNorm (fp16 xn out) ----------------
__global__ void gated_ln_k(const float* __restrict__ y, const float* __restrict__ res,
                           const float* __restrict__ gw, const float* __restrict__ lng,
                           const float* __restrict__ lnb, float* __restrict__ xout,
                           __half* __restrict__ xnout, int n)
{
    int w = (blockIdx.x * blockDim.x + threadIdx.x) >> 5;
    int lane = threadIdx.x & 31;
    if (w >= n) return;
    const float* yp = y + (size_t)w * DIM;
    const float* rp = res + (size_t)w * DIM;
    float yv[8], rv[8];
    float s = 0.f;
#pragma unroll
    for (int j = 0; j < 8; j++) {
        int d = lane + j * 32;
        yv[j] = yp[d];
        rv[j] = rp[d];
        s += yv[j] * gw[d] + rv[j] * gw[DIM + d] + (yv[j] - rv[j]) * gw[2 * DIM + d];
    }
#pragma unroll
    for (int o = 16; o; o >>= 1) s += __shfl_xor_sync(0xffffffffu, s, o);
    float gate = 1.f / (1.f + expf(-s));
    float gr[8], sum = 0.f, sq = 0.f;
#pragma unroll
    for (int j = 0; j < 8; j++) {
        gr[j] = yv[j] * gate + rv[j] * (1.f - gate);
        sum += gr[j];
        sq += gr[j] * gr[j];
    }
#pragma unroll
    for (int o = 16; o; o >>= 1) {
        sum += __shfl_xor_sync(0xffffffffu, sum, o);
        sq += __shfl_xor_sync(0xffffffffu, sq, o);
    }
    float mean = sum * (1.f / DIM);
    float var = sq * (1.f / DIM) - mean * mean;
    float rstd = rsqrtf(var + LNEPS);
#pragma unroll
    for (int j = 0; j < 8; j++) {
        int d = lane + j * 32;
        xout[(size_t)w * DIM + d] = gr[j];
        xnout[(size_t)w * DIM + d] = __float2half_rn((gr[j] - mean) * rstd * lng[d] + lnb[d]);
    }
}

// ---------------- plain gated residual (last use only) ----------------
__global__ void gated_residual_k(const float* __restrict__ y, const float* __restrict__ res,
                                 const float* __restrict__ gw, float* __restrict__ xout, int n)
{
    int w = (blockIdx.x * blockDim.x + threadIdx.x) >> 5;
    int lane = threadIdx.x & 31;
    if (w >= n) return;
    const float* yp = y + (size_t)w * DIM;
    const float* rp = res + (size_t)w * DIM;
    float s = 0.f;
#pragma unroll
    for (int j = 0; j < 8; j++) {
        int d = lane + j * 32;
        float yv = yp[d], rv = rp[d];
        s += yv * gw[d] + rv * gw[DIM + d] + (yv - rv) * gw[2 * DIM + d];
    }
#pragma unroll
    for (int o = 16; o; o >>= 1) s += __shfl_xor_sync(0xffffffffu, s, o);
    float gate = 1.f / (1.f + expf(-s));
#pragma unroll
    for (int j = 0; j < 8; j++) {
        int d = lane + j * 32;
        float yv = yp[d], rv = rp[d];
        xout[(size_t)w * DIM + d] = yv * gate + rv * (1.f - gate);
    }
}

// ---------------- attention (fp16 qkv gathers) ----------------
__global__ void sim_exp_den_k(const __half* __restrict__ qkv,
                              const __nv_bfloat16* __restrict__ eb,
                              const int* __restrict__ srcI, const int* __restrict__ dstI,
                              float* __restrict__ pbuf, float* __restrict__ den, int ne)
{
    int w = (blockIdx.x * blockDim.x + threadIdx.x) >> 5;
    int lane = threadIdx.x & 31;
    if (w >= ne) return;
    int s = srcI[w], d = dstI[w];
    int off = lane * 8;
    uint4 qu = *reinterpret_cast<const uint4*>(qkv + (size_t)d * 768 + off);
    uint4 ku = *reinterpret_cast<const uint4*>(qkv + (size_t)s * 768 + 256 + off);
    uint4 eu = *reinterpret_cast<const uint4*>(eb + (size_t)w * INNER + off);
    float2 q0 = h2f2(qu.x), q1 = h2f2(qu.y), q2 = h2f2(qu.z), q3 = h2f2(qu.w);
    float2 k0 = h2f2(ku.x), k1 = h2f2(ku.y), k2 = h2f2(ku.z), k3 = h2f2(ku.w);
    float2 e0 = bf2f2(eu.x), e1 = bf2f2(eu.y), e2 = bf2f2(eu.z), e3 = bf2f2(eu.w);
    float dot = q0.x * (k0.x + e0.x) + q0.y * (k0.y + e0.y)
              + q1.x * (k1.x + e1.x) + q1.y * (k1.y + e1.y)
              + q2.x * (k2.x + e2.x) + q2.y * (k2.y + e2.y)
              + q3.x * (k3.x + e3.x) + q3.y * (k3.y + e3.y);
    dot += __shfl_xor_sync(0xffffffffu, dot, 1);
    dot += __shfl_xor_sync(0xffffffffu, dot, 2);
    dot += __shfl_xor_sync(0xffffffffu, dot, 4);
    if ((lane & 7) == 0) {
        int h = lane >> 3;
        float p = __expf(dot * 0.125f);
        pbuf[w * HEADS + h] = p;
        atomicAdd(&den[d * HEADS + h], p);
    }
}

__global__ void attn_agg_k(const __half* __restrict__ qkv,
                           const __nv_bfloat16* __restrict__ eb,
                           const float* __restrict__ p, const float* __restrict__ den,
                           const int* __restrict__ srcI, const int* __restrict__ dstI,
                           float* __restrict__ agg, int ne)
{
    int w = (blockIdx.x * blockDim.x + threadIdx.x) >> 5;
    int lane = threadIdx.x & 31;
    if (w >= ne) return;
    int s = srcI[w], d = dstI[w];
    int head = lane >> 3;
    int off = lane * 8;
    float attn = p[w * HEADS + head] / den[d * HEADS + head];
    uint4 vu = *reinterpret_cast<const uint4*>(qkv + (size_t)s * 768 + 512 + off);
    uint4 eu = *reinterpret_cast<const uint4*>(eb + (size_t)w * INNER + off);
    float2 v0 = h2f2(vu.x), v1 = h2f2(vu.y), v2 = h2f2(vu.z), v3 = h2f2(vu.w);
    float2 e0 = bf2f2(eu.x), e1 = bf2f2(eu.y), e2 = bf2f2(eu.z), e3 = bf2f2(eu.w);
    float* base = agg + (size_t)d * INNER + off;
    asm volatile("red.global.add.v4.f32 [%0], {%1,%2,%3,%4};"
                 :: "l"(base), "f"(attn * (v0.x + e0.x)), "f"(attn * (v0.y + e0.y)),
                    "f"(attn * (v1.x + e1.x)), "f"(attn * (v1.y + e1.y)) : "memory");
    asm volatile("red.global.add.v4.f32 [%0], {%1,%2,%3,%4};"
                 :: "l"(base + 4), "f"(attn * (v2.x + e2.x)), "f"(attn * (v2.y + e2.y)),
                    "f"(attn * (v3.x + e3.x)), "f"(attn * (v3.y + e3.y)) : "memory");
}

// ---------------- host side ----------------
static inline dim3 gemm_grid(int M, int N) { return dim3((N + 127) / 128, (M + 127) / 128); }

extern "C" void kernel_launch(void* const* d_in, const int* in_sizes, int n_in,
                              void* d_out, int out_size)
{
    const float* x_in      = (const float*)d_in[0];
    const float* edge_attr = (const float*)d_in[1];
    const int*   edge_idx  = (const int*)d_in[2];
    const float* ln1_g = (const float*)d_in[3];
    const float* ln1_b = (const float*)d_in[4];
    const float* Wq  = (const float*)d_in[5];
    const float* bq  = (const float*)d_in[6];
    const float* Wkv = (const float*)d_in[7];
    const float* bkv = (const float*)d_in[8];
    const float* We  = (const float*)d_in[9];
    const float* be  = (const float*)d_in[10];
    const float* Wo  = (const float*)d_in[11];
    const float* bo  = (const float*)d_in[12];
    const float* gate_attn_W = (const float*)d_in[13];
    const float* ln2_g = (const float*)d_in[14];
    const float* ln2_b = (const float*)d_in[15];
    const float* Wff1 = (const float*)d_in[16];
    const float* bff1 = (const float*)d_in[17];
    const float* Wff2 = (const float*)d_in[18];
    const float* bff2 = (const float*)d_in[19];
    const float* gate_ff_W = (const float*)d_in[20];
    const float* Wproj = (const float*)d_in[21];
    const float* bproj = (const float*)d_in[22];
    float* out = (float*)d_out;

    const int* src = edge_idx;
    const int* dst = edge_idx + EE;

    float *px, *pp, *pden, *pagg, *py, *pwt, *pbqkv;
    __half *pxnh, *pqkvh, *peah, *pffh, *pwth;
    __nv_bfloat16* pe;
    cudaGetSymbolAddress((void**)&px, g_x);
    cudaGetSymbolAddress((void**)&pxnh, g_xnh);
    cudaGetSymbolAddress((void**)&pqkvh, g_qkvh);
    cudaGetSymbolAddress((void**)&peah, g_eah);
    cudaGetSymbolAddress((void**)&pe, g_e);
    cudaGetSymbolAddress((void**)&pp, g_p);
    cudaGetSymbolAddress((void**)&pden, g_den);
    cudaGetSymbolAddress((void**)&pagg, g_agg);
    cudaGetSymbolAddress((void**)&py, g_y);
    cudaGetSymbolAddress((void**)&pffh, g_ffh);
    cudaGetSymbolAddress((void**)&pwt, g_wt);
    cudaGetSymbolAddress((void**)&pwth, g_wth);
    cudaGetSymbolAddress((void**)&pbqkv, g_bqkv);

    static bool attr_set = false;
    if (!attr_set) {
        cudaFuncSetAttribute(tgemm_v4, cudaFuncAttributeMaxDynamicSharedMemorySize, SMEM_BYTES);
        cudaFuncSetAttribute(tgemm_h16<0>, cudaFuncAttributeMaxDynamicSharedMemorySize, HSMEM_BYTES);
        cudaFuncSetAttribute(tgemm_h16<1>, cudaFuncAttributeMaxDynamicSharedMemorySize, HSMEM_BYTES);
        cudaFuncSetAttribute(tgemm_h16<2>, cudaFuncAttributeMaxDynamicSharedMemorySize, HSMEM_BYTES);
        cudaFuncSetAttribute(tgemm_h16<3>, cudaFuncAttributeMaxDynamicSharedMemorySize, HSMEM_BYTES);
        attr_set = true;
    }

    cudaMemcpyAsync(px, x_in, (size_t)NN * DIM * sizeof(float), cudaMemcpyDeviceToDevice, 0);

    cvt_all_k<<<(WT_TOTAL + 255) / 256, 256>>>(Wq, Wkv, We, Wo, Wff1, Wff2, Wproj, pwt, pwth,
                                               bq, bkv, pbqkv);
    {
        size_t n8 = (size_t)EE * EDIM / 8;
        cvt_ea_k<<<(unsigned)((n8 + 255) / 256), 256>>>(edge_attr, peah);
    }

    const int warpBlocks_N = (NN * 32 + 255) / 256;
    const int warpBlocks_E = (EE * 32 + 255) / 256;

    layernorm_k<<<warpBlocks_N, 256>>>(px, ln1_g, ln1_b, pxnh, NN);

    for (int d = 0; d < DEPTH; d++) {
        const __half* wqkvh = pwth + (size_t)d * DIM * 3 * INNER;
        const __half* weh   = pwth + 393216 + (size_t)d * EDIM * INNER;
        const __half* wf1h  = pwth + 655360 + (size_t)d * DIM * FF;
        const __half* wf2h  = pwth + 1179648 + (size_t)d * FF * DIM;
        const float* bed = be + d * INNER;
        const float* wo  = pwt + WO_OFF + (size_t)d * INNER * DIM;
        const float* bod = bo + d * DIM;
        const float* gaw = gate_attn_W + (size_t)d * 3 * DIM;
        const float* l2g = ln2_g + d * DIM;
        const float* l2b = ln2_b + d * DIM;
        const float* bf1 = bff1 + d * FF;
        const float* bf2 = bff2 + d * DIM;
        const float* gfw = gate_ff_W + (size_t)d * 3 * DIM;

        tgemm_h16<3><<<gemm_grid(NN, 3 * INNER), 256, HSMEM_BYTES>>>(
            pxnh, wqkvh, pbqkv + d * 768, pqkvh, NN, 3 * INNER, DIM);
        tgemm_h16<2><<<gemm_grid(EE, INNER), 256, HSMEM_BYTES>>>(
            peah, weh, bed, pe, EE, INNER, EDIM);

        cudaMemsetAsync(pden, 0, (size_t)NN * HEADS * sizeof(float), 0);
        cudaMemsetAsync(pagg, 0, (size_t)NN * INNER * sizeof(float), 0);
        sim_exp_den_k<<<warpBlocks_E, 256>>>(pqkvh, pe, src, dst, pp, pden, EE);
        attn_agg_k<<<warpBlocks_E, 256>>>(pqkvh, pe, pp, pden, src, dst, pagg, EE);

        tgemm_v4<<<gemm_grid(NN, DIM), 128, SMEM_BYTES>>>(pagg, wo, bod, py, NN, DIM, INNER);
        gated_ln_k<<<warpBlocks_N, 256>>>(py, px, gaw, l2g, l2b, px, pxnh, NN);

        tgemm_h16<1><<<gemm_grid(NN, FF), 256, HSMEM_BYTES>>>(
            pxnh, wf1h, bf1, pffh, NN, FF, DIM);
        tgemm_h16<0><<<gemm_grid(NN, DIM), 256, HSMEM_BYTES>>>(
            pffh, wf2h, bf2, py, NN, DIM, FF);

        if (d + 1 < DEPTH) {
            gated_ln_k<<<warpBlocks_N, 256>>>(py, px, gfw,
                                              ln1_g + (d + 1) * DIM, ln1_b + (d + 1) * DIM,
                                              px, pxnh, NN);
        } else {
            gated_residual_k<<<warpBlocks_N, 256>>>(py, px, gfw, px, NN);
        }
    }

    tgemm_v4<<<gemm_grid(NN, OUTD), 128, SMEM_BYTES>>>(px, pwt + WPROJ_OFF, bproj, out, NN, OUTD, DIM);
}

// round 13
// speedup vs baseline: 1.0515x; 1.0515x over previous
#include <cuda_runtime.h>
#include <cuda_bf16.h>
#include <cuda_fp16.h>
#include <cstdint>

// ---------------- problem constants ----------------
#define NN 20000
#define EE 200000
#define DIM 256
#define HEADS 4
#define DH 64
#define INNER 256
#define EDIM 512
#define FF 1024
#define OUTD 128
#define DEPTH 2
#define LNEPS 1e-5f

// ---------------- scratch (device globals; no allocation allowed) ----------------
__device__ float g_x[NN * DIM];
__device__ __half g_xnh[NN * DIM];                    // LN output, fp16
__device__ __half g_qkvh[NN * 3 * INNER];             // [q | k | v] fp16
__device__ __half g_eah[(size_t)EE * EDIM];           // fp16 edge_attr
__device__ __nv_bfloat16 g_e[(size_t)EE * INNER];     // bf16 edge projections
__device__ float g_p[EE * HEADS];
__device__ float g_den[NN * HEADS];
__device__ float g_agg[NN * INNER];
__device__ float g_y[NN * DIM];
__device__ __half g_ffh[NN * FF];                     // GELU out, fp16
__device__ float g_bqkv[DEPTH * 3 * INNER];
// tf32 weights (wo, proj)
#define WQKV_OFF  0
#define WE_OFF    393216
#define WO_OFF    655360
#define WF1_OFF   786432
#define WF2_OFF   1310720
#define WPROJ_OFF 1835008
#define WT_TOTAL  1867776
__device__ float g_wt[WT_TOTAL];
// fp16 weights (qkv, we, ff1, ff2)
#define WTH_TOTAL 1703936
__device__ __half g_wth[WTH_TOTAL];

// ---------------- helpers ----------------
__device__ __forceinline__ uint32_t f2tf32(float f)
{
    uint32_t r;
    asm("cvt.rna.tf32.f32 %0, %1;" : "=r"(r) : "f"(f));
    return r;
}

__device__ __forceinline__ void mma_tf32(float* c, const uint32_t* a, const uint32_t* b)
{
    asm volatile(
        "mma.sync.aligned.m16n8k8.row.col.f32.tf32.tf32.f32 "
        "{%0,%1,%2,%3}, {%4,%5,%6,%7}, {%8,%9}, {%0,%1,%2,%3};"
        : "+f"(c[0]), "+f"(c[1]), "+f"(c[2]), "+f"(c[3])
        : "r"(a[0]), "r"(a[1]), "r"(a[2]), "r"(a[3]), "r"(b[0]), "r"(b[1]));
}

__device__ __forceinline__ void mma_f16(float* c, const uint32_t* a, const uint32_t* b)
{
    asm volatile(
        "mma.sync.aligned.m16n8k16.row.col.f32.f16.f16.f32 "
        "{%0,%1,%2,%3}, {%4,%5,%6,%7}, {%8,%9}, {%0,%1,%2,%3};"
        : "+f"(c[0]), "+f"(c[1]), "+f"(c[2]), "+f"(c[3])
        : "r"(a[0]), "r"(a[1]), "r"(a[2]), "r"(a[3]), "r"(b[0]), "r"(b[1]));
}

__device__ __forceinline__ uint32_t smem_u32(const void* p)
{
    return (uint32_t)__cvta_generic_to_shared(p);
}

__device__ __forceinline__ float2 bf2f2(uint32_t u)
{
    __nv_bfloat162 h = *reinterpret_cast<__nv_bfloat162*>(&u);
    return __bfloat1622float2(h);
}

__device__ __forceinline__ float2 h2f2(uint32_t u)
{
    __half2 h = *reinterpret_cast<__half2*>(&u);
    return __half22float2(h);
}

__device__ __forceinline__ float gelu_f(float v)
{
    float c3 = v * v * v;
    return 0.5f * v * (1.f + tanhf(0.7978845608028654f * (v + 0.044715f * c3)));
}

// ---------------- TF32 GEMM v4 (wo + proj; unchanged) ----------------
#define AS_STRIDE 36
#define BS_STRIDE 136
#define STAGE_WORDS (128 * AS_STRIDE + 32 * BS_STRIDE)
#define SMEM_WORDS (3 * STAGE_WORDS)
#define SMEM_BYTES (SMEM_WORDS * 4)

__global__ __launch_bounds__(128, 2) void tgemm_v4(
    const float* __restrict__ A, const float* __restrict__ B,
    const float* __restrict__ bias, float* __restrict__ C,
    int M, int N, int K)
{
    extern __shared__ uint32_t smem[];
    const int tid = threadIdx.x;
    const int warp = tid >> 5, lane = tid & 31;
    const int warpM = warp >> 1, warpN = warp & 1;
    const int g = lane >> 2, tg = lane & 3;
    const int row0 = blockIdx.y * 128, col0 = blockIdx.x * 128;
    const int lm_row = (lane & 7) + ((lane >> 3) & 1) * 8;
    const int lm_col = (lane >> 4) * 4;

    float acc[4][8][4];
#pragma unroll
    for (int i = 0; i < 4; i++)
#pragma unroll
        for (int j = 0; j < 8; j++)
#pragma unroll
            for (int r = 0; r < 4; r++) acc[i][j][r] = 0.f;

    auto stage = [&](int buf, int k0) {
        uint32_t* As = smem + (size_t)buf * STAGE_WORDS;
        uint32_t* Bs = As + 128 * AS_STRIDE;
#pragma unroll
        for (int i = 0; i < 8; i++) {
            int c = tid + 128 * i;
            int r = c >> 3, cc = (c & 7) * 4;
            int grow = row0 + r;
            int sz = (grow < M) ? 16 : 0;
            if (grow >= M) grow = M - 1;
            const float* src = A + (size_t)grow * K + k0 + cc;
            uint32_t dstp = smem_u32(&As[r * AS_STRIDE + cc]);
            asm volatile("cp.async.cg.shared.global [%0], [%1], 16, %2;"
                         :: "r"(dstp), "l"(src), "r"(sz));
        }
#pragma unroll
        for (int i = 0; i < 8; i++) {
            int c = tid + 128 * i;
            int r = c >> 5, cc = (c & 31) * 4;
            const float* src = B + (size_t)(k0 + r) * N + col0 + cc;
            uint32_t dstp = smem_u32(&Bs[r * BS_STRIDE + cc]);
            asm volatile("cp.async.cg.shared.global [%0], [%1], 16, 16;"
                         :: "r"(dstp), "l"(src));
        }
        asm volatile("cp.async.commit_group;");
    };

    const int nk = K >> 5;
    stage(0, 0);
    stage(1, 32);

    int buf = 0;
    for (int t = 0; t < nk; t++) {
        if (t + 2 < nk) stage((t + 2) % 3, (t + 2) * 32);
        int rem = nk - 1 - t;
        if (rem >= 2)      asm volatile("cp.async.wait_group 2;");
        else if (rem == 1) asm volatile("cp.async.wait_group 1;");
        else               asm volatile("cp.async.wait_group 0;");
        __syncthreads();

        const uint32_t* Ab = smem + (size_t)buf * STAGE_WORDS;
        const uint32_t* Bb = Ab + 128 * AS_STRIDE;

#pragma unroll
        for (int ks = 0; ks < 4; ks++) {
            const int kk = ks * 8;
            uint32_t a[4][4], b[8][2];
#pragma unroll
            for (int mf = 0; mf < 4; mf++) {
                int m0 = warpM * 64 + mf * 16;
                uint32_t addr = smem_u32(&Ab[(m0 + lm_row) * AS_STRIDE + kk + lm_col]);
                asm volatile("ldmatrix.sync.aligned.m8n8.x4.shared.b16 {%0,%1,%2,%3}, [%4];"
                             : "=r"(a[mf][0]), "=r"(a[mf][1]), "=r"(a[mf][2]), "=r"(a[mf][3])
                             : "r"(addr));
            }
#pragma unroll
            for (int nf = 0; nf < 8; nf++) {
                int n = warpN * 64 + nf * 8 + g;
                b[nf][0] = Bb[(kk + tg) * BS_STRIDE + n];
                b[nf][1] = Bb[(kk + tg + 4) * BS_STRIDE + n];
            }
#pragma unroll
            for (int mf = 0; mf < 4; mf++)
#pragma unroll
                for (int nf = 0; nf < 8; nf++)
                    mma_tf32(acc[mf][nf], a[mf], b[nf]);
        }
        __syncthreads();
        buf = (buf + 1) % 3;
    }

#pragma unroll
    for (int mf = 0; mf < 4; mf++) {
#pragma unroll
        for (int half = 0; half < 2; half++) {
            int row = row0 + warpM * 64 + mf * 16 + g + half * 8;
            if (row >= M) continue;
#pragma unroll
            for (int nf = 0; nf < 8; nf++) {
                int col = col0 + warpN * 64 + nf * 8 + 2 * tg;
                float v0 = acc[mf][nf][half * 2 + 0] + bias[col];
                float v1 = acc[mf][nf][half * 2 + 1] + bias[col + 1];
                *reinterpret_cast<float2*>(C + (size_t)row * N + col) = make_float2(v0, v1);
            }
        }
    }
}

// ---------------- FP16 GEMM (R11-proven: 128 thr, 4 warps 2x2, warp tile 64x64) ----------------
// EPI: 0 = bias -> fp32; 1 = bias+GELU -> fp16; 2 = bias -> bf16; 3 = bias -> fp16
#define HA_STRIDE 40
#define HB_STRIDE 136
#define HSTAGE (128 * HA_STRIDE + 32 * HB_STRIDE)
#define HSMEM_BYTES (3 * HSTAGE * 2)

template <int EPI>
__global__ __launch_bounds__(128, 2) void tgemm_h16(
    const __half* __restrict__ A, const __half* __restrict__ B,
    const float* __restrict__ bias, void* __restrict__ C,
    int M, int N, int K)
{
    extern __shared__ __half hsmem[];
    const int tid = threadIdx.x;
    const int warp = tid >> 5, lane = tid & 31;
    const int warpM = warp >> 1, warpN = warp & 1;
    const int g = lane >> 2, tg = lane & 3;
    const int row0 = blockIdx.y * 128, col0 = blockIdx.x * 128;
    const int lm_row = (lane & 7) + ((lane >> 3) & 1) * 8;
    const int lm_col = (lane >> 4) * 8;

    float acc[4][8][4];
#pragma unroll
    for (int i = 0; i < 4; i++)
#pragma unroll
        for (int j = 0; j < 8; j++)
#pragma unroll
            for (int r = 0; r < 4; r++) acc[i][j][r] = 0.f;

    auto stage = [&](int buf, int k0) {
        __half* As = hsmem + (size_t)buf * HSTAGE;
        __half* Bs = As + 128 * HA_STRIDE;
#pragma unroll
        for (int i = 0; i < 4; i++) {
            int c = tid + 128 * i;
            int r = c >> 2, cc = (c & 3) * 8;
            int grow = row0 + r;
            int sz = (grow < M) ? 16 : 0;
            if (grow >= M) grow = M - 1;
            const __half* src = A + (size_t)grow * K + k0 + cc;
            uint32_t dstp = smem_u32(&As[r * HA_STRIDE + cc]);
            asm volatile("cp.async.cg.shared.global [%0], [%1], 16, %2;"
                         :: "r"(dstp), "l"(src), "r"(sz));
        }
#pragma unroll
        for (int i = 0; i < 4; i++) {
            int c = tid + 128 * i;
            int r = c >> 4, cc = (c & 15) * 8;
            const __half* src = B + (size_t)(k0 + r) * N + col0 + cc;
            uint32_t dstp = smem_u32(&Bs[r * HB_STRIDE + cc]);
            asm volatile("cp.async.cg.shared.global [%0], [%1], 16, 16;"
                         :: "r"(dstp), "l"(src));
        }
        asm volatile("cp.async.commit_group;");
    };

    const int nk = K >> 5;
    stage(0, 0);
    stage(1, 32);

    int buf = 0;
    for (int t = 0; t < nk; t++) {
        if (t + 2 < nk) stage((t + 2) % 3, (t + 2) * 32);
        int rem = nk - 1 - t;
        if (rem >= 2)      asm volatile("cp.async.wait_group 2;");
        else if (rem == 1) asm volatile("cp.async.wait_group 1;");
        else               asm volatile("cp.async.wait_group 0;");
        __syncthreads();

        const __half* Ab = hsmem + (size_t)buf * HSTAGE;
        const __half* Bb = Ab + 128 * HA_STRIDE;

#pragma unroll
        for (int ks = 0; ks < 2; ks++) {
            const int kk = ks * 16;
            uint32_t a[4][4], b[8][2];
#pragma unroll
            for (int mf = 0; mf < 4; mf++) {
                int m0 = warpM * 64 + mf * 16;
                uint32_t addr = smem_u32(&Ab[(m0 + lm_row) * HA_STRIDE + kk + lm_col]);
                asm volatile("ldmatrix.sync.aligned.m8n8.x4.shared.b16 {%0,%1,%2,%3}, [%4];"
                             : "=r"(a[mf][0]), "=r"(a[mf][1]), "=r"(a[mf][2]), "=r"(a[mf][3])
                             : "r"(addr));
            }
#pragma unroll
            for (int nf2 = 0; nf2 < 4; nf2++) {
                int n0 = warpN * 64 + nf2 * 16;
                int brow = kk + (lane & 7) + ((lane >> 3) & 1) * 8;
                int bcol = n0 + (lane >> 4) * 8;
                uint32_t addr = smem_u32(&Bb[brow * HB_STRIDE + bcol]);
                asm volatile("ldmatrix.sync.aligned.m8n8.x4.trans.shared.b16 {%0,%1,%2,%3}, [%4];"
                             : "=r"(b[2 * nf2][0]), "=r"(b[2 * nf2][1]),
                               "=r"(b[2 * nf2 + 1][0]), "=r"(b[2 * nf2 + 1][1])
                             : "r"(addr));
            }
#pragma unroll
            for (int mf = 0; mf < 4; mf++)
#pragma unroll
                for (int nf = 0; nf < 8; nf++)
                    mma_f16(acc[mf][nf], a[mf], b[nf]);
        }
        __syncthreads();
        buf = (buf + 1) % 3;
    }

#pragma unroll
    for (int mf = 0; mf < 4; mf++) {
#pragma unroll
        for (int half = 0; half < 2; half++) {
            int row = row0 + warpM * 64 + mf * 16 + g + half * 8;
            if (row >= M) continue;
#pragma unroll
            for (int nf = 0; nf < 8; nf++) {
                int col = col0 + warpN * 64 + nf * 8 + 2 * tg;
                float v0 = acc[mf][nf][half * 2 + 0] + bias[col];
                float v1 = acc[mf][nf][half * 2 + 1] + bias[col + 1];
                if (EPI == 0) {
                    *reinterpret_cast<float2*>(
                        reinterpret_cast<float*>(C) + (size_t)row * N + col) = make_float2(v0, v1);
                } else if (EPI == 1) {
                    v0 = gelu_f(v0);
                    v1 = gelu_f(v1);
                    __half2 h = __floats2half2_rn(v0, v1);
                    *reinterpret_cast<__half2*>(
                        reinterpret_cast<__half*>(C) + (size_t)row * N + col) = h;
                } else if (EPI == 2) {
                    __nv_bfloat162 h = __floats2bfloat162_rn(v0, v1);
                    *reinterpret_cast<__nv_bfloat162*>(
                        reinterpret_cast<__nv_bfloat16*>(C) + (size_t)row * N + col) = h;
                } else {
                    __half2 h = __floats2half2_rn(v0, v1);
                    *reinterpret_cast<__half2*>(
                        reinterpret_cast<__half*>(C) + (size_t)row * N + col) = h;
                }
            }
        }
    }
}

// ---------------- edge_attr fp32 -> fp16 ----------------
__global__ void cvt_ea_k(const float* __restrict__ in, __half* __restrict__ out)
{
    size_t i = (size_t)blockIdx.x * blockDim.x + threadIdx.x;
    size_t n8 = (size_t)EE * EDIM / 8;
    if (i >= n8) return;
    const float4* p = reinterpret_cast<const float4*>(in) + i * 2;
    float4 v0 = p[0], v1 = p[1];
    __half2 h0 = __floats2half2_rn(v0.x, v0.y);
    __half2 h1 = __floats2half2_rn(v0.z, v0.w);
    __half2 h2 = __floats2half2_rn(v1.x, v1.y);
    __half2 h3 = __floats2half2_rn(v1.z, v1.w);
    uint4 u;
    u.x = *reinterpret_cast<uint32_t*>(&h0);
    u.y = *reinterpret_cast<uint32_t*>(&h1);
    u.z = *reinterpret_cast<uint32_t*>(&h2);
    u.w = *reinterpret_cast<uint32_t*>(&h3);
    reinterpret_cast<uint4*>(out)[i] = u;
}

// ---------------- fused weight conversion + bias concat ----------------
__global__ void cvt_all_k(const float* __restrict__ Wq, const float* __restrict__ Wkv,
                          const float* __restrict__ We, const float* __restrict__ Wo,
                          const float* __restrict__ Wf1, const float* __restrict__ Wf2,
                          const float* __restrict__ Wp, float* __restrict__ out,
                          __half* __restrict__ outh,
                          const float* __restrict__ bq, const float* __restrict__ bkv,
                          float* __restrict__ bqkv)
{
    int i = blockIdx.x * blockDim.x + threadIdx.x;
    if (i < DEPTH * 3 * INNER) {
        int d = i / (3 * INNER), c = i % (3 * INNER);
        bqkv[i] = (c < INNER) ? bq[d * INNER + c] : bkv[d * 2 * INNER + (c - INNER)];
    }
    if (i >= WT_TOTAL) return;
    float v;
    if (i < WE_OFF) {
        int t = i;
        int d = t / (DIM * 3 * INNER);
        int r = (t / (3 * INNER)) % DIM;
        int c = t % (3 * INNER);
        v = (c < INNER) ? Wq[((size_t)d * DIM + r) * INNER + c]
                        : Wkv[((size_t)d * DIM + r) * (2 * INNER) + (c - INNER)];
    } else if (i < WO_OFF) v = We[i - WE_OFF];
    else if (i < WF1_OFF) v = Wo[i - WO_OFF];
    else if (i < WF2_OFF) v = Wf1[i - WF1_OFF];
    else if (i < WPROJ_OFF) v = Wf2[i - WF2_OFF];
    else v = Wp[i - WPROJ_OFF];
    out[i] = __uint_as_float(f2tf32(v));
    if (i < WO_OFF) outh[i] = __float2half_rn(v);
    else if (i >= WF1_OFF && i < WPROJ_OFF) outh[i - 131072] = __float2half_rn(v);
}

// ---------------- LayerNorm (fp16 out; first use only) ----------------
__global__ void layernorm_k(const float* __restrict__ x, const float* __restrict__ g,
                            const float* __restrict__ b, __half* __restrict__ out, int n)
{
    int w = (blockIdx.x * blockDim.x + threadIdx.x) >> 5;
    int lane = threadIdx.x & 31;
    if (w >= n) return;
    const float* xp = x + (size_t)w * DIM;
    float v[8], s = 0.f, sq = 0.f;
#pragma unroll
    for (int j = 0; j < 8; j++) {
        v[j] = xp[lane + j * 32];
        s += v[j];
        sq += v[j] * v[j];
    }
#pragma unroll
    for (int o = 16; o; o >>= 1) {
        s += __shfl_xor_sync(0xffffffffu, s, o);
        sq += __shfl_xor_sync(0xffffffffu, sq, o);
    }
    float mean = s * (1.f / DIM);
    float var = sq * (1.f / DIM) - mean * mean;
    float rstd = rsqrtf(var + LNEPS);
#pragma unroll
    for (int j = 0; j < 8; j++) {
        int d = lane + j * 32;
        out[(size_t)w * DIM + d] = __float2half_rn((v[j] - mean) * rstd * g[d] + b[d]);
    }
}

// ---------------- fused gated residual + LayerNorm (fp16 xn out) ----------------
__global__ void gated_ln_k(const float* __restrict__ y, const float* __restrict__ res,
                           const float* __restrict__ gw, const float* __restrict__ lng,
                           const float* __restrict__ lnb, float* __restrict__ xout,
                           __half* __restrict__ xnout, int n)
{
    int w = (blockIdx.x * blockDim.x + threadIdx.x) >> 5;
    int lane = threadIdx.x & 31;
    if (w >= n) return;
    const float* yp = y + (size_t)w * DIM;
    const float* rp = res + (size_t)w * DIM;
    float yv[8], rv[8];
    float s = 0.f;
#pragma unroll
    for (int j = 0; j < 8; j++) {
        int d = lane + j * 32;
        yv[j] = yp[d];
        rv[j] = rp[d];
        s += yv[j] * gw[d] + rv[j] * gw[DIM + d] + (yv[j] - rv[j]) * gw[2 * DIM + d];
    }
#pragma unroll
    for (int o = 16; o; o >>= 1) s += __shfl_xor_sync(0xffffffffu, s, o);
    float gate = 1.f / (1.f + expf(-s));
    float gr[8], sum = 0.f, sq = 0.f;
#pragma unroll
    for (int j = 0; j < 8; j++) {
        gr[j] = yv[j] * gate + rv[j] * (1.f - gate);
        sum += gr[j];
        sq += gr[j] * gr[j];
    }
#pragma unroll
    for (int o = 16; o; o >>= 1) {
        sum += __shfl_xor_sync(0xffffffffu, sum, o);
        sq += __shfl_xor_sync(0xffffffffu, sq, o);
    }
    float mean = sum * (1.f / DIM);
    float var = sq * (1.f / DIM) - mean * mean;
    float rstd = rsqrtf(var + LNEPS);
#pragma unroll
    for (int j = 0; j < 8; j++) {
        int d = lane + j * 32;
        xout[(size_t)w * DIM + d] = gr[j];
        xnout[(size_t)w * DIM + d] = __float2half_rn((gr[j] - mean) * rstd * lng[d] + lnb[d]);
    }
}

// ---------------- plain gated residual (last use only) ----------------
__global__ void gated_residual_k(const float* __restrict__ y, const float* __restrict__ res,
                                 const float* __restrict__ gw, float* __restrict__ xout, int n)
{
    int w = (blockIdx.x * blockDim.x + threadIdx.x) >> 5;
    int lane = threadIdx.x & 31;
    if (w >= n) return;
    const float* yp = y + (size_t)w * DIM;
    const float* rp = res + (size_t)w * DIM;
    float s = 0.f;
#pragma unroll
    for (int j = 0; j < 8; j++) {
        int d = lane + j * 32;
        float yv = yp[d], rv = rp[d];
        s += yv * gw[d] + rv * gw[DIM + d] + (yv - rv) * gw[2 * DIM + d];
    }
#pragma unroll
    for (int o = 16; o; o >>= 1) s += __shfl_xor_sync(0xffffffffu, s, o);
    float gate = 1.f / (1.f + expf(-s));
#pragma unroll
    for (int j = 0; j < 8; j++) {
        int d = lane + j * 32;
        float yv = yp[d], rv = rp[d];
        xout[(size_t)w * DIM + d] = yv * gate + rv * (1.f - gate);
    }
}

// ---------------- attention (fp16 qkv gathers) ----------------
__global__ void sim_exp_den_k(const __half* __restrict__ qkv,
                              const __nv_bfloat16* __restrict__ eb,
                              const int* __restrict__ srcI, const int* __restrict__ dstI,
                              float* __restrict__ pbuf, float* __restrict__ den, int ne)
{
    int w = (blockIdx.x * blockDim.x + threadIdx.x) >> 5;
    int lane = threadIdx.x & 31;
    if (w >= ne) return;
    int s = srcI[w], d = dstI[w];
    int off = lane * 8;
    uint4 qu = *reinterpret_cast<const uint4*>(qkv + (size_t)d * 768 + off);
    uint4 ku = *reinterpret_cast<const uint4*>(qkv + (size_t)s * 768 + 256 + off);
    uint4 eu = *reinterpret_cast<const uint4*>(eb + (size_t)w * INNER + off);
    float2 q0 = h2f2(qu.x), q1 = h2f2(qu.y), q2 = h2f2(qu.z), q3 = h2f2(qu.w);
    float2 k0 = h2f2(ku.x), k1 = h2f2(ku.y), k2 = h2f2(ku.z), k3 = h2f2(ku.w);
    float2 e0 = bf2f2(eu.x), e1 = bf2f2(eu.y), e2 = bf2f2(eu.z), e3 = bf2f2(eu.w);
    float dot = q0.x * (k0.x + e0.x) + q0.y * (k0.y + e0.y)
              + q1.x * (k1.x + e1.x) + q1.y * (k1.y + e1.y)
              + q2.x * (k2.x + e2.x) + q2.y * (k2.y + e2.y)
              + q3.x * (k3.x + e3.x) + q3.y * (k3.y + e3.y);
    dot += __shfl_xor_sync(0xffffffffu, dot, 1);
    dot += __shfl_xor_sync(0xffffffffu, dot, 2);
    dot += __shfl_xor_sync(0xffffffffu, dot, 4);
    if ((lane & 7) == 0) {
        int h = lane >> 3;
        float p = __expf(dot * 0.125f);
        pbuf[w * HEADS + h] = p;
        atomicAdd(&den[d * HEADS + h], p);
    }
}

__global__ void attn_agg_k(const __half* __restrict__ qkv,
                           const __nv_bfloat16* __restrict__ eb,
                           const float* __restrict__ p, const float* __restrict__ den,
                           const int* __restrict__ srcI, const int* __restrict__ dstI,
                           float* __restrict__ agg, int ne)
{
    int w = (blockIdx.x * blockDim.x + threadIdx.x) >> 5;
    int lane = threadIdx.x & 31;
    if (w >= ne) return;
    int s = srcI[w], d = dstI[w];
    int head = lane >> 3;
    int off = lane * 8;
    float attn = p[w * HEADS + head] / den[d * HEADS + head];
    uint4 vu = *reinterpret_cast<const uint4*>(qkv + (size_t)s * 768 + 512 + off);
    uint4 eu = *reinterpret_cast<const uint4*>(eb + (size_t)w * INNER + off);
    float2 v0 = h2f2(vu.x), v1 = h2f2(vu.y), v2 = h2f2(vu.z), v3 = h2f2(vu.w);
    float2 e0 = bf2f2(eu.x), e1 = bf2f2(eu.y), e2 = bf2f2(eu.z), e3 = bf2f2(eu.w);
    float* base = agg + (size_t)d * INNER + off;
    asm volatile("red.global.add.v4.f32 [%0], {%1,%2,%3,%4};"
                 :: "l"(base), "f"(attn * (v0.x + e0.x)), "f"(attn * (v0.y + e0.y)),
                    "f"(attn * (v1.x + e1.x)), "f"(attn * (v1.y + e1.y)) : "memory");
    asm volatile("red.global.add.v4.f32 [%0], {%1,%2,%3,%4};"
                 :: "l"(base + 4), "f"(attn * (v2.x + e2.x)), "f"(attn * (v2.y + e2.y)),
                    "f"(attn * (v3.x + e3.x)), "f"(attn * (v3.y + e3.y)) : "memory");
}

// ---------------- host side ----------------
static inline dim3 gemm_grid(int M, int N) { return dim3((N + 127) / 128, (M + 127) / 128); }

extern "C" void kernel_launch(void* const* d_in, const int* in_sizes, int n_in,
                              void* d_out, int out_size)
{
    const float* x_in      = (const float*)d_in[0];
    const float* edge_attr = (const float*)d_in[1];
    const int*   edge_idx  = (const int*)d_in[2];
    const float* ln1_g = (const float*)d_in[3];
    const float* ln1_b = (const float*)d_in[4];
    const float* Wq  = (const float*)d_in[5];
    const float* bq  = (const float*)d_in[6];
    const float* Wkv = (const float*)d_in[7];
    const float* bkv = (const float*)d_in[8];
    const float* We  = (const float*)d_in[9];
    const float* be  = (const float*)d_in[10];
    const float* Wo  = (const float*)d_in[11];
    const float* bo  = (const float*)d_in[12];
    const float* gate_attn_W = (const float*)d_in[13];
    const float* ln2_g = (const float*)d_in[14];
    const float* ln2_b = (const float*)d_in[15];
    const float* Wff1 = (const float*)d_in[16];
    const float* bff1 = (const float*)d_in[17];
    const float* Wff2 = (const float*)d_in[18];
    const float* bff2 = (const float*)d_in[19];
    const float* gate_ff_W = (const float*)d_in[20];
    const float* Wproj = (const float*)d_in[21];
    const float* bproj = (const float*)d_in[22];
    float* out = (float*)d_out;

    const int* src = edge_idx;
    const int* dst = edge_idx + EE;

    float *px, *pp, *pden, *pagg, *py, *pwt, *pbqkv;
    __half *pxnh, *pqkvh, *peah, *pffh, *pwth;
    __nv_bfloat16* pe;
    cudaGetSymbolAddress((void**)&px, g_x);
    cudaGetSymbolAddress((void**)&pxnh, g_xnh);
    cudaGetSymbolAddress((void**)&pqkvh, g_qkvh);
    cudaGetSymbolAddress((void**)&peah, g_eah);
    cudaGetSymbolAddress((void**)&pe, g_e);
    cudaGetSymbolAddress((void**)&pp, g_p);
    cudaGetSymbolAddress((void**)&pden, g_den);
    cudaGetSymbolAddress((void**)&pagg, g_agg);
    cudaGetSymbolAddress((void**)&py, g_y);
    cudaGetSymbolAddress((void**)&pffh, g_ffh);
    cudaGetSymbolAddress((void**)&pwt, g_wt);
    cudaGetSymbolAddress((void**)&pwth, g_wth);
    cudaGetSymbolAddress((void**)&pbqkv, g_bqkv);

    static bool attr_set = false;
    if (!attr_set) {
        cudaFuncSetAttribute(tgemm_v4, cudaFuncAttributeMaxDynamicSharedMemorySize, SMEM_BYTES);
        cudaFuncSetAttribute(tgemm_h16<0>, cudaFuncAttributeMaxDynamicSharedMemorySize, HSMEM_BYTES);
        cudaFuncSetAttribute(tgemm_h16<1>, cudaFuncAttributeMaxDynamicSharedMemorySize, HSMEM_BYTES);
        cudaFuncSetAttribute(tgemm_h16<2>, cudaFuncAttributeMaxDynamicSharedMemorySize, HSMEM_BYTES);
        cudaFuncSetAttribute(tgemm_h16<3>, cudaFuncAttributeMaxDynamicSharedMemorySize, HSMEM_BYTES);
        attr_set = true;
    }

    cudaMemcpyAsync(px, x_in, (size_t)NN * DIM * sizeof(float), cudaMemcpyDeviceToDevice, 0);

    cvt_all_k<<<(WT_TOTAL + 255) / 256, 256>>>(Wq, Wkv, We, Wo, Wff1, Wff2, Wproj, pwt, pwth,
                                               bq, bkv, pbqkv);
    {
        size_t n8 = (size_t)EE * EDIM / 8;
        cvt_ea_k<<<(unsigned)((n8 + 255) / 256), 256>>>(edge_attr, peah);
    }

    const int warpBlocks_N = (NN * 32 + 255) / 256;
    const int warpBlocks_E = (EE * 32 + 255) / 256;

    layernorm_k<<<warpBlocks_N, 256>>>(px, ln1_g, ln1_b, pxnh, NN);

    for (int d = 0; d < DEPTH; d++) {
        const __half* wqkvh = pwth + (size_t)d * DIM * 3 * INNER;
        const __half* weh   = pwth + 393216 + (size_t)d * EDIM * INNER;
        const __half* wf1h  = pwth + 655360 + (size_t)d * DIM * FF;
        const __half* wf2h  = pwth + 1179648 + (size_t)d * FF * DIM;
        const float* bed = be + d * INNER;
        const float* wo  = pwt + WO_OFF + (size_t)d * INNER * DIM;
        const float* bod = bo + d * DIM;
        const float* gaw = gate_attn_W + (size_t)d * 3 * DIM;
        const float* l2g = ln2_g + d * DIM;
        const float* l2b = ln2_b + d * DIM;
        const float* bf1 = bff1 + d * FF;
        const float* bf2 = bff2 + d * DIM;
        const float* gfw = gate_ff_W + (size_t)d * 3 * DIM;

        tgemm_h16<3><<<gemm_grid(NN, 3 * INNER), 128, HSMEM_BYTES>>>(
            pxnh, wqkvh, pbqkv + d * 768, pqkvh, NN, 3 * INNER, DIM);
        tgemm_h16<2><<<gemm_grid(EE, INNER), 128, HSMEM_BYTES>>>(
            peah, weh, bed, pe, EE, INNER, EDIM);

        cudaMemsetAsync(pden, 0, (size_t)NN * HEADS * sizeof(float), 0);
        cudaMemsetAsync(pagg, 0, (size_t)NN * INNER * sizeof(float), 0);
        sim_exp_den_k<<<warpBlocks_E, 256>>>(pqkvh, pe, src, dst, pp, pden, EE);
        attn_agg_k<<<warpBlocks_E, 256>>>(pqkvh, pe, pp, pden, src, dst, pagg, EE);

        tgemm_v4<<<gemm_grid(NN, DIM), 128, SMEM_BYTES>>>(pagg, wo, bod, py, NN, DIM, INNER);
        gated_ln_k<<<warpBlocks_N, 256>>>(py, px, gaw, l2g, l2b, px, pxnh, NN);

        tgemm_h16<1><<<gemm_grid(NN, FF), 128, HSMEM_BYTES>>>(
            pxnh, wf1h, bf1, pffh, NN, FF, DIM);
        tgemm_h16<0><<<gemm_grid(NN, DIM), 128, HSMEM_BYTES>>>(
            pffh, wf2h, bf2, py, NN, DIM, FF);

        if (d + 1 < DEPTH) {
            gated_ln_k<<<warpBlocks_N, 256>>>(py, px, gfw,
                                              ln1_g + (d + 1) * DIM, ln1_b + (d + 1) * DIM,
                                              px, pxnh, NN);
        } else {
            gated_residual_k<<<warpBlocks_N, 256>>>(py, px, gfw, px, NN);
        }
    }

    tgemm_v4<<<gemm_grid(NN, OUTD), 128, SMEM_BYTES>>>(px, pwt + WPROJ_OFF, bproj, out, NN, OUTD, DIM);
}

// round 14
// speedup vs baseline: 1.1173x; 1.0626x over previous
#include <cuda_runtime.h>
#include <cuda_bf16.h>
#include <cuda_fp16.h>
#include <cstdint>

// ---------------- problem constants ----------------
#define NN 20000
#define EE 200000
#define DIM 256
#define HEADS 4
#define DH 64
#define INNER 256
#define EDIM 512
#define FF 1024
#define OUTD 128
#define DEPTH 2
#define LNEPS 1e-5f

// ---------------- scratch (device globals; no allocation allowed) ----------------
__device__ float g_x[NN * DIM];
__device__ __half g_xnh[NN * DIM];                    // LN output, fp16
__device__ __half g_qkvh[NN * 3 * INNER];             // [q | k | v] fp16
__device__ __half g_eah[(size_t)EE * EDIM];           // fp16 edge_attr
__device__ __nv_bfloat16 g_e[(size_t)EE * INNER];     // bf16 edge projections
__device__ float g_den[NN * HEADS];
__device__ float g_agg[NN * INNER];
__device__ float g_y[NN * DIM];
__device__ __half g_ffh[NN * FF];                     // GELU out, fp16
__device__ float g_bqkv[DEPTH * 3 * INNER];
// tf32 weights (wo, proj)
#define WQKV_OFF  0
#define WE_OFF    393216
#define WO_OFF    655360
#define WF1_OFF   786432
#define WF2_OFF   1310720
#define WPROJ_OFF 1835008
#define WT_TOTAL  1867776
__device__ float g_wt[WT_TOTAL];
// fp16 weights (qkv, we, ff1, ff2)
#define WTH_TOTAL 1703936
__device__ __half g_wth[WTH_TOTAL];

// ---------------- helpers ----------------
__device__ __forceinline__ uint32_t f2tf32(float f)
{
    uint32_t r;
    asm("cvt.rna.tf32.f32 %0, %1;" : "=r"(r) : "f"(f));
    return r;
}

__device__ __forceinline__ void mma_tf32(float* c, const uint32_t* a, const uint32_t* b)
{
    asm volatile(
        "mma.sync.aligned.m16n8k8.row.col.f32.tf32.tf32.f32 "
        "{%0,%1,%2,%3}, {%4,%5,%6,%7}, {%8,%9}, {%0,%1,%2,%3};"
        : "+f"(c[0]), "+f"(c[1]), "+f"(c[2]), "+f"(c[3])
        : "r"(a[0]), "r"(a[1]), "r"(a[2]), "r"(a[3]), "r"(b[0]), "r"(b[1]));
}

__device__ __forceinline__ void mma_f16(float* c, const uint32_t* a, const uint32_t* b)
{
    asm volatile(
        "mma.sync.aligned.m16n8k16.row.col.f32.f16.f16.f32 "
        "{%0,%1,%2,%3}, {%4,%5,%6,%7}, {%8,%9}, {%0,%1,%2,%3};"
        : "+f"(c[0]), "+f"(c[1]), "+f"(c[2]), "+f"(c[3])
        : "r"(a[0]), "r"(a[1]), "r"(a[2]), "r"(a[3]), "r"(b[0]), "r"(b[1]));
}

__device__ __forceinline__ uint32_t smem_u32(const void* p)
{
    return (uint32_t)__cvta_generic_to_shared(p);
}

__device__ __forceinline__ float2 bf2f2(uint32_t u)
{
    __nv_bfloat162 h = *reinterpret_cast<__nv_bfloat162*>(&u);
    return __bfloat1622float2(h);
}

__device__ __forceinline__ float2 h2f2(uint32_t u)
{
    __half2 h = *reinterpret_cast<__half2*>(&u);
    return __half22float2(h);
}

__device__ __forceinline__ float gelu_f(float v)
{
    float c3 = v * v * v;
    return 0.5f * v * (1.f + tanhf(0.7978845608028654f * (v + 0.044715f * c3)));
}

// ---------------- TF32 GEMM v4 (wo + proj; unchanged) ----------------
#define AS_STRIDE 36
#define BS_STRIDE 136
#define STAGE_WORDS (128 * AS_STRIDE + 32 * BS_STRIDE)
#define SMEM_WORDS (3 * STAGE_WORDS)
#define SMEM_BYTES (SMEM_WORDS * 4)

__global__ __launch_bounds__(128, 2) void tgemm_v4(
    const float* __restrict__ A, const float* __restrict__ B,
    const float* __restrict__ bias, float* __restrict__ C,
    int M, int N, int K)
{
    extern __shared__ uint32_t smem[];
    const int tid = threadIdx.x;
    const int warp = tid >> 5, lane = tid & 31;
    const int warpM = warp >> 1, warpN = warp & 1;
    const int g = lane >> 2, tg = lane & 3;
    const int row0 = blockIdx.y * 128, col0 = blockIdx.x * 128;
    const int lm_row = (lane & 7) + ((lane >> 3) & 1) * 8;
    const int lm_col = (lane >> 4) * 4;

    float acc[4][8][4];
#pragma unroll
    for (int i = 0; i < 4; i++)
#pragma unroll
        for (int j = 0; j < 8; j++)
#pragma unroll
            for (int r = 0; r < 4; r++) acc[i][j][r] = 0.f;

    auto stage = [&](int buf, int k0) {
        uint32_t* As = smem + (size_t)buf * STAGE_WORDS;
        uint32_t* Bs = As + 128 * AS_STRIDE;
#pragma unroll
        for (int i = 0; i < 8; i++) {
            int c = tid + 128 * i;
            int r = c >> 3, cc = (c & 7) * 4;
            int grow = row0 + r;
            int sz = (grow < M) ? 16 : 0;
            if (grow >= M) grow = M - 1;
            const float* src = A + (size_t)grow * K + k0 + cc;
            uint32_t dstp = smem_u32(&As[r * AS_STRIDE + cc]);
            asm volatile("cp.async.cg.shared.global [%0], [%1], 16, %2;"
                         :: "r"(dstp), "l"(src), "r"(sz));
        }
#pragma unroll
        for (int i = 0; i < 8; i++) {
            int c = tid + 128 * i;
            int r = c >> 5, cc = (c & 31) * 4;
            const float* src = B + (size_t)(k0 + r) * N + col0 + cc;
            uint32_t dstp = smem_u32(&Bs[r * BS_STRIDE + cc]);
            asm volatile("cp.async.cg.shared.global [%0], [%1], 16, 16;"
                         :: "r"(dstp), "l"(src));
        }
        asm volatile("cp.async.commit_group;");
    };

    const int nk = K >> 5;
    stage(0, 0);
    stage(1, 32);

    int buf = 0;
    for (int t = 0; t < nk; t++) {
        if (t + 2 < nk) stage((t + 2) % 3, (t + 2) * 32);
        int rem = nk - 1 - t;
        if (rem >= 2)      asm volatile("cp.async.wait_group 2;");
        else if (rem == 1) asm volatile("cp.async.wait_group 1;");
        else               asm volatile("cp.async.wait_group 0;");
        __syncthreads();

        const uint32_t* Ab = smem + (size_t)buf * STAGE_WORDS;
        const uint32_t* Bb = Ab + 128 * AS_STRIDE;

#pragma unroll
        for (int ks = 0; ks < 4; ks++) {
            const int kk = ks * 8;
            uint32_t a[4][4], b[8][2];
#pragma unroll
            for (int mf = 0; mf < 4; mf++) {
                int m0 = warpM * 64 + mf * 16;
                uint32_t addr = smem_u32(&Ab[(m0 + lm_row) * AS_STRIDE + kk + lm_col]);
                asm volatile("ldmatrix.sync.aligned.m8n8.x4.shared.b16 {%0,%1,%2,%3}, [%4];"
                             : "=r"(a[mf][0]), "=r"(a[mf][1]), "=r"(a[mf][2]), "=r"(a[mf][3])
                             : "r"(addr));
            }
#pragma unroll
            for (int nf = 0; nf < 8; nf++) {
                int n = warpN * 64 + nf * 8 + g;
                b[nf][0] = Bb[(kk + tg) * BS_STRIDE + n];
                b[nf][1] = Bb[(kk + tg + 4) * BS_STRIDE + n];
            }
#pragma unroll
            for (int mf = 0; mf < 4; mf++)
#pragma unroll
                for (int nf = 0; nf < 8; nf++)
                    mma_tf32(acc[mf][nf], a[mf], b[nf]);
        }
        __syncthreads();
        buf = (buf + 1) % 3;
    }

#pragma unroll
    for (int mf = 0; mf < 4; mf++) {
#pragma unroll
        for (int half = 0; half < 2; half++) {
            int row = row0 + warpM * 64 + mf * 16 + g + half * 8;
            if (row >= M) continue;
#pragma unroll
            for (int nf = 0; nf < 8; nf++) {
                int col = col0 + warpN * 64 + nf * 8 + 2 * tg;
                float v0 = acc[mf][nf][half * 2 + 0] + bias[col];
                float v1 = acc[mf][nf][half * 2 + 1] + bias[col + 1];
                *reinterpret_cast<float2*>(C + (size_t)row * N + col) = make_float2(v0, v1);
            }
        }
    }
}

// ---------------- FP16 GEMM (128 thr, 4 warps 2x2, warp tile 64x64) ----------------
// EPI: 0 = bias -> fp32; 1 = bias+GELU -> fp16; 2 = bias -> bf16; 3 = bias -> fp16
#define HA_STRIDE 40
#define HB_STRIDE 136
#define HSTAGE (128 * HA_STRIDE + 32 * HB_STRIDE)
#define HSMEM_BYTES (3 * HSTAGE * 2)

template <int EPI>
__global__ __launch_bounds__(128, 2) void tgemm_h16(
    const __half* __restrict__ A, const __half* __restrict__ B,
    const float* __restrict__ bias, void* __restrict__ C,
    int M, int N, int K)
{
    extern __shared__ __half hsmem[];
    const int tid = threadIdx.x;
    const int warp = tid >> 5, lane = tid & 31;
    const int warpM = warp >> 1, warpN = warp & 1;
    const int g = lane >> 2, tg = lane & 3;
    const int row0 = blockIdx.y * 128, col0 = blockIdx.x * 128;
    const int lm_row = (lane & 7) + ((lane >> 3) & 1) * 8;
    const int lm_col = (lane >> 4) * 8;

    float acc[4][8][4];
#pragma unroll
    for (int i = 0; i < 4; i++)
#pragma unroll
        for (int j = 0; j < 8; j++)
#pragma unroll
            for (int r = 0; r < 4; r++) acc[i][j][r] = 0.f;

    auto stage = [&](int buf, int k0) {
        __half* As = hsmem + (size_t)buf * HSTAGE;
        __half* Bs = As + 128 * HA_STRIDE;
#pragma unroll
        for (int i = 0; i < 4; i++) {
            int c = tid + 128 * i;
            int r = c >> 2, cc = (c & 3) * 8;
            int grow = row0 + r;
            int sz = (grow < M) ? 16 : 0;
            if (grow >= M) grow = M - 1;
            const __half* src = A + (size_t)grow * K + k0 + cc;
            uint32_t dstp = smem_u32(&As[r * HA_STRIDE + cc]);
            asm volatile("cp.async.cg.shared.global [%0], [%1], 16, %2;"
                         :: "r"(dstp), "l"(src), "r"(sz));
        }
#pragma unroll
        for (int i = 0; i < 4; i++) {
            int c = tid + 128 * i;
            int r = c >> 4, cc = (c & 15) * 8;
            const __half* src = B + (size_t)(k0 + r) * N + col0 + cc;
            uint32_t dstp = smem_u32(&Bs[r * HB_STRIDE + cc]);
            asm volatile("cp.async.cg.shared.global [%0], [%1], 16, 16;"
                         :: "r"(dstp), "l"(src));
        }
        asm volatile("cp.async.commit_group;");
    };

    const int nk = K >> 5;
    stage(0, 0);
    stage(1, 32);

    int buf = 0;
    for (int t = 0; t < nk; t++) {
        if (t + 2 < nk) stage((t + 2) % 3, (t + 2) * 32);
        int rem = nk - 1 - t;
        if (rem >= 2)      asm volatile("cp.async.wait_group 2;");
        else if (rem == 1) asm volatile("cp.async.wait_group 1;");
        else               asm volatile("cp.async.wait_group 0;");
        __syncthreads();

        const __half* Ab = hsmem + (size_t)buf * HSTAGE;
        const __half* Bb = Ab + 128 * HA_STRIDE;

#pragma unroll
        for (int ks = 0; ks < 2; ks++) {
            const int kk = ks * 16;
            uint32_t a[4][4], b[8][2];
#pragma unroll
            for (int mf = 0; mf < 4; mf++) {
                int m0 = warpM * 64 + mf * 16;
                uint32_t addr = smem_u32(&Ab[(m0 + lm_row) * HA_STRIDE + kk + lm_col]);
                asm volatile("ldmatrix.sync.aligned.m8n8.x4.shared.b16 {%0,%1,%2,%3}, [%4];"
                             : "=r"(a[mf][0]), "=r"(a[mf][1]), "=r"(a[mf][2]), "=r"(a[mf][3])
                             : "r"(addr));
            }
#pragma unroll
            for (int nf2 = 0; nf2 < 4; nf2++) {
                int n0 = warpN * 64 + nf2 * 16;
                int brow = kk + (lane & 7) + ((lane >> 3) & 1) * 8;
                int bcol = n0 + (lane >> 4) * 8;
                uint32_t addr = smem_u32(&Bb[brow * HB_STRIDE + bcol]);
                asm volatile("ldmatrix.sync.aligned.m8n8.x4.trans.shared.b16 {%0,%1,%2,%3}, [%4];"
                             : "=r"(b[2 * nf2][0]), "=r"(b[2 * nf2][1]),
                               "=r"(b[2 * nf2 + 1][0]), "=r"(b[2 * nf2 + 1][1])
                             : "r"(addr));
            }
#pragma unroll
            for (int mf = 0; mf < 4; mf++)
#pragma unroll
                for (int nf = 0; nf < 8; nf++)
                    mma_f16(acc[mf][nf], a[mf], b[nf]);
        }
        __syncthreads();
        buf = (buf + 1) % 3;
    }

#pragma unroll
    for (int mf = 0; mf < 4; mf++) {
#pragma unroll
        for (int half = 0; half < 2; half++) {
            int row = row0 + warpM * 64 + mf * 16 + g + half * 8;
            if (row >= M) continue;
#pragma unroll
            for (int nf = 0; nf < 8; nf++) {
                int col = col0 + warpN * 64 + nf * 8 + 2 * tg;
                float v0 = acc[mf][nf][half * 2 + 0] + bias[col];
                float v1 = acc[mf][nf][half * 2 + 1] + bias[col + 1];
                if (EPI == 0) {
                    *reinterpret_cast<float2*>(
                        reinterpret_cast<float*>(C) + (size_t)row * N + col) = make_float2(v0, v1);
                } else if (EPI == 1) {
                    v0 = gelu_f(v0);
                    v1 = gelu_f(v1);
                    __half2 h = __floats2half2_rn(v0, v1);
                    *reinterpret_cast<__half2*>(
                        reinterpret_cast<__half*>(C) + (size_t)row * N + col) = h;
                } else if (EPI == 2) {
                    __nv_bfloat162 h = __floats2bfloat162_rn(v0, v1);
                    *reinterpret_cast<__nv_bfloat162*>(
                        reinterpret_cast<__nv_bfloat16*>(C) + (size_t)row * N + col) = h;
                } else {
                    __half2 h = __floats2half2_rn(v0, v1);
                    *reinterpret_cast<__half2*>(
                        reinterpret_cast<__half*>(C) + (size_t)row * N + col) = h;
                }
            }
        }
    }
}

// ---------------- edge_attr fp32 -> fp16 ----------------
__global__ void cvt_ea_k(const float* __restrict__ in, __half* __restrict__ out)
{
    size_t i = (size_t)blockIdx.x * blockDim.x + threadIdx.x;
    size_t n8 = (size_t)EE * EDIM / 8;
    if (i >= n8) return;
    const float4* p = reinterpret_cast<const float4*>(in) + i * 2;
    float4 v0 = p[0], v1 = p[1];
    __half2 h0 = __floats2half2_rn(v0.x, v0.y);
    __half2 h1 = __floats2half2_rn(v0.z, v0.w);
    __half2 h2 = __floats2half2_rn(v1.x, v1.y);
    __half2 h3 = __floats2half2_rn(v1.z, v1.w);
    uint4 u;
    u.x = *reinterpret_cast<uint32_t*>(&h0);
    u.y = *reinterpret_cast<uint32_t*>(&h1);
    u.z = *reinterpret_cast<uint32_t*>(&h2);
    u.w = *reinterpret_cast<uint32_t*>(&h3);
    reinterpret_cast<uint4*>(out)[i] = u;
}

// ---------------- fused weight conversion + bias concat ----------------
__global__ void cvt_all_k(const float* __restrict__ Wq, const float* __restrict__ Wkv,
                          const float* __restrict__ We, const float* __restrict__ Wo,
                          const float* __restrict__ Wf1, const float* __restrict__ Wf2,
                          const float* __restrict__ Wp, float* __restrict__ out,
                          __half* __restrict__ outh,
                          const float* __restrict__ bq, const float* __restrict__ bkv,
                          float* __restrict__ bqkv)
{
    int i = blockIdx.x * blockDim.x + threadIdx.x;
    if (i < DEPTH * 3 * INNER) {
        int d = i / (3 * INNER), c = i % (3 * INNER);
        bqkv[i] = (c < INNER) ? bq[d * INNER + c] : bkv[d * 2 * INNER + (c - INNER)];
    }
    if (i >= WT_TOTAL) return;
    float v;
    if (i < WE_OFF) {
        int t = i;
        int d = t / (DIM * 3 * INNER);
        int r = (t / (3 * INNER)) % DIM;
        int c = t % (3 * INNER);
        v = (c < INNER) ? Wq[((size_t)d * DIM + r) * INNER + c]
                        : Wkv[((size_t)d * DIM + r) * (2 * INNER) + (c - INNER)];
    } else if (i < WO_OFF) v = We[i - WE_OFF];
    else if (i < WF1_OFF) v = Wo[i - WO_OFF];
    else if (i < WF2_OFF) v = Wf1[i - WF1_OFF];
    else if (i < WPROJ_OFF) v = Wf2[i - WF2_OFF];
    else v = Wp[i - WPROJ_OFF];
    out[i] = __uint_as_float(f2tf32(v));
    if (i < WO_OFF) outh[i] = __float2half_rn(v);
    else if (i >= WF1_OFF && i < WPROJ_OFF) outh[i - 131072] = __float2half_rn(v);
}

// ---------------- LayerNorm (fp16 out; first use only) ----------------
__global__ void layernorm_k(const float* __restrict__ x, const float* __restrict__ g,
                            const float* __restrict__ b, __half* __restrict__ out, int n)
{
    int w = (blockIdx.x * blockDim.x + threadIdx.x) >> 5;
    int lane = threadIdx.x & 31;
    if (w >= n) return;
    const float* xp = x + (size_t)w * DIM;
    float v[8], s = 0.f, sq = 0.f;
#pragma unroll
    for (int j = 0; j < 8; j++) {
        v[j] = xp[lane + j * 32];
        s += v[j];
        sq += v[j] * v[j];
    }
#pragma unroll
    for (int o = 16; o; o >>= 1) {
        s += __shfl_xor_sync(0xffffffffu, s, o);
        sq += __shfl_xor_sync(0xffffffffu, sq, o);
    }
    float mean = s * (1.f / DIM);
    float var = sq * (1.f / DIM) - mean * mean;
    float rstd = rsqrtf(var + LNEPS);
#pragma unroll
    for (int j = 0; j < 8; j++) {
        int d = lane + j * 32;
        out[(size_t)w * DIM + d] = __float2half_rn((v[j] - mean) * rstd * g[d] + b[d]);
    }
}

// ---------------- fused gated residual + LayerNorm (fp16 xn out) ----------------
__global__ void gated_ln_k(const float* __restrict__ y, const float* __restrict__ res,
                           const float* __restrict__ gw, const float* __restrict__ lng,
                           const float* __restrict__ lnb, float* __restrict__ xout,
                           __half* __restrict__ xnout, int n)
{
    int w = (blockIdx.x * blockDim.x + threadIdx.x) >> 5;
    int lane = threadIdx.x & 31;
    if (w >= n) return;
    const float* yp = y + (size_t)w * DIM;
    const float* rp = res + (size_t)w * DIM;
    float yv[8], rv[8];
    float s = 0.f;
#pragma unroll
    for (int j = 0; j < 8; j++) {
        int d = lane + j * 32;
        yv[j] = yp[d];
        rv[j] = rp[d];
        s += yv[j] * gw[d] + rv[j] * gw[DIM + d] + (yv[j] - rv[j]) * gw[2 * DIM + d];
    }
#pragma unroll
    for (int o = 16; o; o >>= 1) s += __shfl_xor_sync(0xffffffffu, s, o);
    float gate = 1.f / (1.f + expf(-s));
    float gr[8], sum = 0.f, sq = 0.f;
#pragma unroll
    for (int j = 0; j < 8; j++) {
        gr[j] = yv[j] * gate + rv[j] * (1.f - gate);
        sum += gr[j];
        sq += gr[j] * gr[j];
    }
#pragma unroll
    for (int o = 16; o; o >>= 1) {
        sum += __shfl_xor_sync(0xffffffffu, sum, o);
        sq += __shfl_xor_sync(0xffffffffu, sq, o);
    }
    float mean = sum * (1.f / DIM);
    float var = sq * (1.f / DIM) - mean * mean;
    float rstd = rsqrtf(var + LNEPS);
#pragma unroll
    for (int j = 0; j < 8; j++) {
        int d = lane + j * 32;
        xout[(size_t)w * DIM + d] = gr[j];
        xnout[(size_t)w * DIM + d] = __float2half_rn((gr[j] - mean) * rstd * lng[d] + lnb[d]);
    }
}

// ---------------- plain gated residual (last use only) ----------------
__global__ void gated_residual_k(const float* __restrict__ y, const float* __restrict__ res,
                                 const float* __restrict__ gw, float* __restrict__ xout, int n)
{
    int w = (blockIdx.x * blockDim.x + threadIdx.x) >> 5;
    int lane = threadIdx.x & 31;
    if (w >= n) return;
    const float* yp = y + (size_t)w * DIM;
    const float* rp = res + (size_t)w * DIM;
    float s = 0.f;
#pragma unroll
    for (int j = 0; j < 8; j++) {
        int d = lane + j * 32;
        float yv = yp[d], rv = rp[d];
        s += yv * gw[d] + rv * gw[DIM + d] + (yv - rv) * gw[2 * DIM + d];
    }
#pragma unroll
    for (int o = 16; o; o >>= 1) s += __shfl_xor_sync(0xffffffffu, s, o);
    float gate = 1.f / (1.f + expf(-s));
#pragma unroll
    for (int j = 0; j < 8; j++) {
        int d = lane + j * 32;
        float yv = yp[d], rv = rp[d];
        xout[(size_t)w * DIM + d] = yv * gate + rv * (1.f - gate);
    }
}

// ---------------- fused attention: sim -> p -> den + unnormalized agg, one pass ----------------
// warp per edge, lane = h*8+j. agg' = sum_e p * (v+e); den = sum_e p.
// Normalization (agg'/den) happens in normalize_agg_k.
__global__ void attn_fused_k(const __half* __restrict__ qkv,
                             const __nv_bfloat16* __restrict__ eb,
                             const int* __restrict__ srcI, const int* __restrict__ dstI,
                             float* __restrict__ den, float* __restrict__ agg, int ne)
{
    int w = (blockIdx.x * blockDim.x + threadIdx.x) >> 5;
    int lane = threadIdx.x & 31;
    if (w >= ne) return;
    int s = srcI[w], d = dstI[w];
    int off = lane * 8;
    uint4 qu = *reinterpret_cast<const uint4*>(qkv + (size_t)d * 768 + off);
    uint4 ku = *reinterpret_cast<const uint4*>(qkv + (size_t)s * 768 + 256 + off);
    uint4 vu = *reinterpret_cast<const uint4*>(qkv + (size_t)s * 768 + 512 + off);
    uint4 eu = *reinterpret_cast<const uint4*>(eb + (size_t)w * INNER + off);
    float2 q0 = h2f2(qu.x), q1 = h2f2(qu.y), q2 = h2f2(qu.z), q3 = h2f2(qu.w);
    float2 k0 = h2f2(ku.x), k1 = h2f2(ku.y), k2 = h2f2(ku.z), k3 = h2f2(ku.w);
    float2 v0 = h2f2(vu.x), v1 = h2f2(vu.y), v2 = h2f2(vu.z), v3 = h2f2(vu.w);
    float2 e0 = bf2f2(eu.x), e1 = bf2f2(eu.y), e2 = bf2f2(eu.z), e3 = bf2f2(eu.w);
    float dot = q0.x * (k0.x + e0.x) + q0.y * (k0.y + e0.y)
              + q1.x * (k1.x + e1.x) + q1.y * (k1.y + e1.y)
              + q2.x * (k2.x + e2.x) + q2.y * (k2.y + e2.y)
              + q3.x * (k3.x + e3.x) + q3.y * (k3.y + e3.y);
    dot += __shfl_xor_sync(0xffffffffu, dot, 1);
    dot += __shfl_xor_sync(0xffffffffu, dot, 2);
    dot += __shfl_xor_sync(0xffffffffu, dot, 4);
    // all lanes in each 8-lane group now hold that head's dot
    float p = __expf(dot * 0.125f);
    if ((lane & 7) == 0)
        atomicAdd(&den[d * HEADS + (lane >> 3)], p);
    float* base = agg + (size_t)d * INNER + off;
    asm volatile("red.global.add.v4.f32 [%0], {%1,%2,%3,%4};"
                 :: "l"(base), "f"(p * (v0.x + e0.x)), "f"(p * (v0.y + e0.y)),
                    "f"(p * (v1.x + e1.x)), "f"(p * (v1.y + e1.y)) : "memory");
    asm volatile("red.global.add.v4.f32 [%0], {%1,%2,%3,%4};"
                 :: "l"(base + 4), "f"(p * (v2.x + e2.x)), "f"(p * (v2.y + e2.y)),
                    "f"(p * (v3.x + e3.x)), "f"(p * (v3.y + e3.y)) : "memory");
}

// agg[i] /= den[node, head]; zero for edgeless nodes (den == 0) to match reference.
__global__ void normalize_agg_k(float* __restrict__ agg, const float* __restrict__ den)
{
    int i = blockIdx.x * blockDim.x + threadIdx.x;   // over NN*INNER/4
    if (i >= NN * INNER / 4) return;
    int node = i >> 6;                 // 64 float4s per node row
    int head = (i & 63) >> 4;          // 16 float4s per head
    float dd = den[node * HEADS + head];
    float inv = (dd > 0.f) ? 1.f / dd : 0.f;
    float4 v = reinterpret_cast<float4*>(agg)[i];
    v.x *= inv; v.y *= inv; v.z *= inv; v.w *= inv;
    reinterpret_cast<float4*>(agg)[i] = v;
}

// ---------------- host side ----------------
static inline dim3 gemm_grid(int M, int N) { return dim3((N + 127) / 128, (M + 127) / 128); }

extern "C" void kernel_launch(void* const* d_in, const int* in_sizes, int n_in,
                              void* d_out, int out_size)
{
    const float* x_in      = (const float*)d_in[0];
    const float* edge_attr = (const float*)d_in[1];
    const int*   edge_idx  = (const int*)d_in[2];
    const float* ln1_g = (const float*)d_in[3];
    const float* ln1_b = (const float*)d_in[4];
    const float* Wq  = (const float*)d_in[5];
    const float* bq  = (const float*)d_in[6];
    const float* Wkv = (const float*)d_in[7];
    const float* bkv = (const float*)d_in[8];
    const float* We  = (const float*)d_in[9];
    const float* be  = (const float*)d_in[10];
    const float* Wo  = (const float*)d_in[11];
    const float* bo  = (const float*)d_in[12];
    const float* gate_attn_W = (const float*)d_in[13];
    const float* ln2_g = (const float*)d_in[14];
    const float* ln2_b = (const float*)d_in[15];
    const float* Wff1 = (const float*)d_in[16];
    const float* bff1 = (const float*)d_in[17];
    const float* Wff2 = (const float*)d_in[18];
    const float* bff2 = (const float*)d_in[19];
    const float* gate_ff_W = (const float*)d_in[20];
    const float* Wproj = (const float*)d_in[21];
    const float* bproj = (const float*)d_in[22];
    float* out = (float*)d_out;

    const int* src = edge_idx;
    const int* dst = edge_idx + EE;

    float *px, *pden, *pagg, *py, *pwt, *pbqkv;
    __half *pxnh, *pqkvh, *peah, *pffh, *pwth;
    __nv_bfloat16* pe;
    cudaGetSymbolAddress((void**)&px, g_x);
    cudaGetSymbolAddress((void**)&pxnh, g_xnh);
    cudaGetSymbolAddress((void**)&pqkvh, g_qkvh);
    cudaGetSymbolAddress((void**)&peah, g_eah);
    cudaGetSymbolAddress((void**)&pe, g_e);
    cudaGetSymbolAddress((void**)&pden, g_den);
    cudaGetSymbolAddress((void**)&pagg, g_agg);
    cudaGetSymbolAddress((void**)&py, g_y);
    cudaGetSymbolAddress((void**)&pffh, g_ffh);
    cudaGetSymbolAddress((void**)&pwt, g_wt);
    cudaGetSymbolAddress((void**)&pwth, g_wth);
    cudaGetSymbolAddress((void**)&pbqkv, g_bqkv);

    static bool attr_set = false;
    if (!attr_set) {
        cudaFuncSetAttribute(tgemm_v4, cudaFuncAttributeMaxDynamicSharedMemorySize, SMEM_BYTES);
        cudaFuncSetAttribute(tgemm_h16<0>, cudaFuncAttributeMaxDynamicSharedMemorySize, HSMEM_BYTES);
        cudaFuncSetAttribute(tgemm_h16<1>, cudaFuncAttributeMaxDynamicSharedMemorySize, HSMEM_BYTES);
        cudaFuncSetAttribute(tgemm_h16<2>, cudaFuncAttributeMaxDynamicSharedMemorySize, HSMEM_BYTES);
        cudaFuncSetAttribute(tgemm_h16<3>, cudaFuncAttributeMaxDynamicSharedMemorySize, HSMEM_BYTES);
        attr_set = true;
    }

    cudaMemcpyAsync(px, x_in, (size_t)NN * DIM * sizeof(float), cudaMemcpyDeviceToDevice, 0);

    cvt_all_k<<<(WT_TOTAL + 255) / 256, 256>>>(Wq, Wkv, We, Wo, Wff1, Wff2, Wproj, pwt, pwth,
                                               bq, bkv, pbqkv);
    {
        size_t n8 = (size_t)EE * EDIM / 8;
        cvt_ea_k<<<(unsigned)((n8 + 255) / 256), 256>>>(edge_attr, peah);
    }

    const int warpBlocks_N = (NN * 32 + 255) / 256;
    const int warpBlocks_E = (EE * 32 + 255) / 256;

    layernorm_k<<<warpBlocks_N, 256>>>(px, ln1_g, ln1_b, pxnh, NN);

    for (int d = 0; d < DEPTH; d++) {
        const __half* wqkvh = pwth + (size_t)d * DIM * 3 * INNER;
        const __half* weh   = pwth + 393216 + (size_t)d * EDIM * INNER;
        const __half* wf1h  = pwth + 655360 + (size_t)d * DIM * FF;
        const __half* wf2h  = pwth + 1179648 + (size_t)d * FF * DIM;
        const float* bed = be + d * INNER;
        const float* wo  = pwt + WO_OFF + (size_t)d * INNER * DIM;
        const float* bod = bo + d * DIM;
        const float* gaw = gate_attn_W + (size_t)d * 3 * DIM;
        const float* l2g = ln2_g + d * DIM;
        const float* l2b = ln2_b + d * DIM;
        const float* bf1 = bff1 + d * FF;
        const float* bf2 = bff2 + d * DIM;
        const float* gfw = gate_ff_W + (size_t)d * 3 * DIM;

        tgemm_h16<3><<<gemm_grid(NN, 3 * INNER), 128, HSMEM_BYTES>>>(
            pxnh, wqkvh, pbqkv + d * 768, pqkvh, NN, 3 * INNER, DIM);
        tgemm_h16<2><<<gemm_grid(EE, INNER), 128, HSMEM_BYTES>>>(
            peah, weh, bed, pe, EE, INNER, EDIM);

        cudaMemsetAsync(pden, 0, (size_t)NN * HEADS * sizeof(float), 0);
        cudaMemsetAsync(pagg, 0, (size_t)NN * INNER * sizeof(float), 0);
        attn_fused_k<<<warpBlocks_E, 256>>>(pqkvh, pe, src, dst, pden, pagg, EE);
        normalize_agg_k<<<(NN * INNER / 4 + 255) / 256, 256>>>(pagg, pden);

        tgemm_v4<<<gemm_grid(NN, DIM), 128, SMEM_BYTES>>>(pagg, wo, bod, py, NN, DIM, INNER);
        gated_ln_k<<<warpBlocks_N, 256>>>(py, px, gaw, l2g, l2b, px, pxnh, NN);

        tgemm_h16<1><<<gemm_grid(NN, FF), 128, HSMEM_BYTES>>>(
            pxnh, wf1h, bf1, pffh, NN, FF, DIM);
        tgemm_h16<0><<<gemm_grid(NN, DIM), 128, HSMEM_BYTES>>>(
            pffh, wf2h, bf2, py, NN, DIM, FF);

        if (d + 1 < DEPTH) {
            gated_ln_k<<<warpBlocks_N, 256>>>(py, px, gfw,
                                              ln1_g + (d + 1) * DIM, ln1_b + (d + 1) * DIM,
                                              px, pxnh, NN);
        } else {
            gated_residual_k<<<warpBlocks_N, 256>>>(py, px, gfw, px, NN);
        }
    }

    tgemm_v4<<<gemm_grid(NN, OUTD), 128, SMEM_BYTES>>>(px, pwt + WPROJ_OFF, bproj, out, NN, OUTD, DIM);
}

// round 15
// speedup vs baseline: 1.1482x; 1.0276x over previous
#include <cuda_runtime.h>
#include <cuda_bf16.h>
#include <cuda_fp16.h>
#include <cstdint>

// ---------------- problem constants ----------------
#define NN 20000
#define EE 200000
#define DIM 256
#define HEADS 4
#define DH 64
#define INNER 256
#define EDIM 512
#define FF 1024
#define OUTD 128
#define DEPTH 2
#define LNEPS 1e-5f

// ---------------- scratch (device globals; no allocation allowed) ----------------
__device__ float g_x[NN * DIM];
__device__ __half g_xnh[NN * DIM];
__device__ __half g_qkvh[NN * 3 * INNER];
__device__ __half g_eah[(size_t)EE * EDIM];
__device__ __nv_bfloat16 g_e0[(size_t)EE * INNER];    // layer-0 edge projections
__device__ __nv_bfloat16 g_e1[(size_t)EE * INNER];    // layer-1 edge projections
__device__ float g_den[NN * HEADS];
__device__ float g_agg[NN * INNER];
__device__ float g_y[NN * DIM];
__device__ __half g_ffh[NN * FF];
__device__ float g_bqkv[DEPTH * 3 * INNER];
// tf32 weights (wo, proj)
#define WQKV_OFF  0
#define WE_OFF    393216
#define WO_OFF    655360
#define WF1_OFF   786432
#define WF2_OFF   1310720
#define WPROJ_OFF 1835008
#define WT_TOTAL  1867776
__device__ float g_wt[WT_TOTAL];
// fp16 weights (qkv, we, ff1, ff2)
#define WTH_TOTAL 1703936
__device__ __half g_wth[WTH_TOTAL];

// ---------------- helpers ----------------
__device__ __forceinline__ uint32_t f2tf32(float f)
{
    uint32_t r;
    asm("cvt.rna.tf32.f32 %0, %1;" : "=r"(r) : "f"(f));
    return r;
}

__device__ __forceinline__ void mma_tf32(float* c, const uint32_t* a, const uint32_t* b)
{
    asm volatile(
        "mma.sync.aligned.m16n8k8.row.col.f32.tf32.tf32.f32 "
        "{%0,%1,%2,%3}, {%4,%5,%6,%7}, {%8,%9}, {%0,%1,%2,%3};"
        : "+f"(c[0]), "+f"(c[1]), "+f"(c[2]), "+f"(c[3])
        : "r"(a[0]), "r"(a[1]), "r"(a[2]), "r"(a[3]), "r"(b[0]), "r"(b[1]));
}

__device__ __forceinline__ void mma_f16(float* c, const uint32_t* a, const uint32_t* b)
{
    asm volatile(
        "mma.sync.aligned.m16n8k16.row.col.f32.f16.f16.f32 "
        "{%0,%1,%2,%3}, {%4,%5,%6,%7}, {%8,%9}, {%0,%1,%2,%3};"
        : "+f"(c[0]), "+f"(c[1]), "+f"(c[2]), "+f"(c[3])
        : "r"(a[0]), "r"(a[1]), "r"(a[2]), "r"(a[3]), "r"(b[0]), "r"(b[1]));
}

__device__ __forceinline__ uint32_t smem_u32(const void* p)
{
    return (uint32_t)__cvta_generic_to_shared(p);
}

__device__ __forceinline__ float2 bf2f2(uint32_t u)
{
    __nv_bfloat162 h = *reinterpret_cast<__nv_bfloat162*>(&u);
    return __bfloat1622float2(h);
}

__device__ __forceinline__ float2 h2f2(uint32_t u)
{
    __half2 h = *reinterpret_cast<__half2*>(&u);
    return __half22float2(h);
}

__device__ __forceinline__ float gelu_f(float v)
{
    float c3 = v * v * v;
    return 0.5f * v * (1.f + tanhf(0.7978845608028654f * (v + 0.044715f * c3)));
}

// ---------------- TF32 GEMM v4 (wo + proj) ----------------
#define AS_STRIDE 36
#define BS_STRIDE 136
#define STAGE_WORDS (128 * AS_STRIDE + 32 * BS_STRIDE)
#define SMEM_WORDS (3 * STAGE_WORDS)
#define SMEM_BYTES (SMEM_WORDS * 4)

__global__ __launch_bounds__(128, 2) void tgemm_v4(
    const float* __restrict__ A, const float* __restrict__ B,
    const float* __restrict__ bias, float* __restrict__ C,
    int M, int N, int K)
{
    extern __shared__ uint32_t smem[];
    const int tid = threadIdx.x;
    const int warp = tid >> 5, lane = tid & 31;
    const int warpM = warp >> 1, warpN = warp & 1;
    const int g = lane >> 2, tg = lane & 3;
    const int row0 = blockIdx.y * 128, col0 = blockIdx.x * 128;
    const int lm_row = (lane & 7) + ((lane >> 3) & 1) * 8;
    const int lm_col = (lane >> 4) * 4;

    float acc[4][8][4];
#pragma unroll
    for (int i = 0; i < 4; i++)
#pragma unroll
        for (int j = 0; j < 8; j++)
#pragma unroll
            for (int r = 0; r < 4; r++) acc[i][j][r] = 0.f;

    auto stage = [&](int buf, int k0) {
        uint32_t* As = smem + (size_t)buf * STAGE_WORDS;
        uint32_t* Bs = As + 128 * AS_STRIDE;
#pragma unroll
        for (int i = 0; i < 8; i++) {
            int c = tid + 128 * i;
            int r = c >> 3, cc = (c & 7) * 4;
            int grow = row0 + r;
            int sz = (grow < M) ? 16 : 0;
            if (grow >= M) grow = M - 1;
            const float* src = A + (size_t)grow * K + k0 + cc;
            uint32_t dstp = smem_u32(&As[r * AS_STRIDE + cc]);
            asm volatile("cp.async.cg.shared.global [%0], [%1], 16, %2;"
                         :: "r"(dstp), "l"(src), "r"(sz));
        }
#pragma unroll
        for (int i = 0; i < 8; i++) {
            int c = tid + 128 * i;
            int r = c >> 5, cc = (c & 31) * 4;
            const float* src = B + (size_t)(k0 + r) * N + col0 + cc;
            uint32_t dstp = smem_u32(&Bs[r * BS_STRIDE + cc]);
            asm volatile("cp.async.cg.shared.global [%0], [%1], 16, 16;"
                         :: "r"(dstp), "l"(src));
        }
        asm volatile("cp.async.commit_group;");
    };

    const int nk = K >> 5;
    stage(0, 0);
    stage(1, 32);

    int buf = 0;
    for (int t = 0; t < nk; t++) {
        if (t + 2 < nk) stage((t + 2) % 3, (t + 2) * 32);
        int rem = nk - 1 - t;
        if (rem >= 2)      asm volatile("cp.async.wait_group 2;");
        else if (rem == 1) asm volatile("cp.async.wait_group 1;");
        else               asm volatile("cp.async.wait_group 0;");
        __syncthreads();

        const uint32_t* Ab = smem + (size_t)buf * STAGE_WORDS;
        const uint32_t* Bb = Ab + 128 * AS_STRIDE;

#pragma unroll
        for (int ks = 0; ks < 4; ks++) {
            const int kk = ks * 8;
            uint32_t a[4][4], b[8][2];
#pragma unroll
            for (int mf = 0; mf < 4; mf++) {
                int m0 = warpM * 64 + mf * 16;
                uint32_t addr = smem_u32(&Ab[(m0 + lm_row) * AS_STRIDE + kk + lm_col]);
                asm volatile("ldmatrix.sync.aligned.m8n8.x4.shared.b16 {%0,%1,%2,%3}, [%4];"
                             : "=r"(a[mf][0]), "=r"(a[mf][1]), "=r"(a[mf][2]), "=r"(a[mf][3])
                             : "r"(addr));
            }
#pragma unroll
            for (int nf = 0; nf < 8; nf++) {
                int n = warpN * 64 + nf * 8 + g;
                b[nf][0] = Bb[(kk + tg) * BS_STRIDE + n];
                b[nf][1] = Bb[(kk + tg + 4) * BS_STRIDE + n];
            }
#pragma unroll
            for (int mf = 0; mf < 4; mf++)
#pragma unroll
                for (int nf = 0; nf < 8; nf++)
                    mma_tf32(acc[mf][nf], a[mf], b[nf]);
        }
        __syncthreads();
        buf = (buf + 1) % 3;
    }

#pragma unroll
    for (int mf = 0; mf < 4; mf++) {
#pragma unroll
        for (int half = 0; half < 2; half++) {
            int row = row0 + warpM * 64 + mf * 16 + g + half * 8;
            if (row >= M) continue;
#pragma unroll
            for (int nf = 0; nf < 8; nf++) {
                int col = col0 + warpN * 64 + nf * 8 + 2 * tg;
                float v0 = acc[mf][nf][half * 2 + 0] + bias[col];
                float v1 = acc[mf][nf][half * 2 + 1] + bias[col + 1];
                *reinterpret_cast<float2*>(C + (size_t)row * N + col) = make_float2(v0, v1);
            }
        }
    }
}

// ---------------- FP16 GEMM (128 thr, 4 warps 2x2, warp tile 64x64) ----------------
#define HA_STRIDE 40
#define HB_STRIDE 136
#define HSTAGE (128 * HA_STRIDE + 32 * HB_STRIDE)
#define HSMEM_BYTES (3 * HSTAGE * 2)

template <int EPI>
__global__ __launch_bounds__(128, 2) void tgemm_h16(
    const __half* __restrict__ A, const __half* __restrict__ B,
    const float* __restrict__ bias, void* __restrict__ C,
    int M, int N, int K)
{
    extern __shared__ __half hsmem[];
    const int tid = threadIdx.x;
    const int warp = tid >> 5, lane = tid & 31;
    const int warpM = warp >> 1, warpN = warp & 1;
    const int g = lane >> 2, tg = lane & 3;
    const int row0 = blockIdx.y * 128, col0 = blockIdx.x * 128;
    const int lm_row = (lane & 7) + ((lane >> 3) & 1) * 8;
    const int lm_col = (lane >> 4) * 8;

    float acc[4][8][4];
#pragma unroll
    for (int i = 0; i < 4; i++)
#pragma unroll
        for (int j = 0; j < 8; j++)
#pragma unroll
            for (int r = 0; r < 4; r++) acc[i][j][r] = 0.f;

    auto stage = [&](int buf, int k0) {
        __half* As = hsmem + (size_t)buf * HSTAGE;
        __half* Bs = As + 128 * HA_STRIDE;
#pragma unroll
        for (int i = 0; i < 4; i++) {
            int c = tid + 128 * i;
            int r = c >> 2, cc = (c & 3) * 8;
            int grow = row0 + r;
            int sz = (grow < M) ? 16 : 0;
            if (grow >= M) grow = M - 1;
            const __half* src = A + (size_t)grow * K + k0 + cc;
            uint32_t dstp = smem_u32(&As[r * HA_STRIDE + cc]);
            asm volatile("cp.async.cg.shared.global [%0], [%1], 16, %2;"
                         :: "r"(dstp), "l"(src), "r"(sz));
        }
#pragma unroll
        for (int i = 0; i < 4; i++) {
            int c = tid + 128 * i;
            int r = c >> 4, cc = (c & 15) * 8;
            const __half* src = B + (size_t)(k0 + r) * N + col0 + cc;
            uint32_t dstp = smem_u32(&Bs[r * HB_STRIDE + cc]);
            asm volatile("cp.async.cg.shared.global [%0], [%1], 16, 16;"
                         :: "r"(dstp), "l"(src));
        }
        asm volatile("cp.async.commit_group;");
    };

    const int nk = K >> 5;
    stage(0, 0);
    stage(1, 32);

    int buf = 0;
    for (int t = 0; t < nk; t++) {
        if (t + 2 < nk) stage((t + 2) % 3, (t + 2) * 32);
        int rem = nk - 1 - t;
        if (rem >= 2)      asm volatile("cp.async.wait_group 2;");
        else if (rem == 1) asm volatile("cp.async.wait_group 1;");
        else               asm volatile("cp.async.wait_group 0;");
        __syncthreads();

        const __half* Ab = hsmem + (size_t)buf * HSTAGE;
        const __half* Bb = Ab + 128 * HA_STRIDE;

#pragma unroll
        for (int ks = 0; ks < 2; ks++) {
            const int kk = ks * 16;
            uint32_t a[4][4], b[8][2];
#pragma unroll
            for (int mf = 0; mf < 4; mf++) {
                int m0 = warpM * 64 + mf * 16;
                uint32_t addr = smem_u32(&Ab[(m0 + lm_row) * HA_STRIDE + kk + lm_col]);
                asm volatile("ldmatrix.sync.aligned.m8n8.x4.shared.b16 {%0,%1,%2,%3}, [%4];"
                             : "=r"(a[mf][0]), "=r"(a[mf][1]), "=r"(a[mf][2]), "=r"(a[mf][3])
                             : "r"(addr));
            }
#pragma unroll
            for (int nf2 = 0; nf2 < 4; nf2++) {
                int n0 = warpN * 64 + nf2 * 16;
                int brow = kk + (lane & 7) + ((lane >> 3) & 1) * 8;
                int bcol = n0 + (lane >> 4) * 8;
                uint32_t addr = smem_u32(&Bb[brow * HB_STRIDE + bcol]);
                asm volatile("ldmatrix.sync.aligned.m8n8.x4.trans.shared.b16 {%0,%1,%2,%3}, [%4];"
                             : "=r"(b[2 * nf2][0]), "=r"(b[2 * nf2][1]),
                               "=r"(b[2 * nf2 + 1][0]), "=r"(b[2 * nf2 + 1][1])
                             : "r"(addr));
            }
#pragma unroll
            for (int mf = 0; mf < 4; mf++)
#pragma unroll
                for (int nf = 0; nf < 8; nf++)
                    mma_f16(acc[mf][nf], a[mf], b[nf]);
        }
        __syncthreads();
        buf = (buf + 1) % 3;
    }

#pragma unroll
    for (int mf = 0; mf < 4; mf++) {
#pragma unroll
        for (int half = 0; half < 2; half++) {
            int row = row0 + warpM * 64 + mf * 16 + g + half * 8;
            if (row >= M) continue;
#pragma unroll
            for (int nf = 0; nf < 8; nf++) {
                int col = col0 + warpN * 64 + nf * 8 + 2 * tg;
                float v0 = acc[mf][nf][half * 2 + 0] + bias[col];
                float v1 = acc[mf][nf][half * 2 + 1] + bias[col + 1];
                if (EPI == 0) {
                    *reinterpret_cast<float2*>(
                        reinterpret_cast<float*>(C) + (size_t)row * N + col) = make_float2(v0, v1);
                } else if (EPI == 1) {
                    v0 = gelu_f(v0);
                    v1 = gelu_f(v1);
                    __half2 h = __floats2half2_rn(v0, v1);
                    *reinterpret_cast<__half2*>(
                        reinterpret_cast<__half*>(C) + (size_t)row * N + col) = h;
                } else if (EPI == 2) {
                    __nv_bfloat162 h = __floats2bfloat162_rn(v0, v1);
                    *reinterpret_cast<__nv_bfloat162*>(
                        reinterpret_cast<__nv_bfloat16*>(C) + (size_t)row * N + col) = h;
                } else {
                    __half2 h = __floats2half2_rn(v0, v1);
                    *reinterpret_cast<__half2*>(
                        reinterpret_cast<__half*>(C) + (size_t)row * N + col) = h;
                }
            }
        }
    }
}

// ---------------- edge_attr fp32 -> fp16 ----------------
__global__ void cvt_ea_k(const float* __restrict__ in, __half* __restrict__ out)
{
    size_t i = (size_t)blockIdx.x * blockDim.x + threadIdx.x;
    size_t n8 = (size_t)EE * EDIM / 8;
    if (i >= n8) return;
    const float4* p = reinterpret_cast<const float4*>(in) + i * 2;
    float4 v0 = p[0], v1 = p[1];
    __half2 h0 = __floats2half2_rn(v0.x, v0.y);
    __half2 h1 = __floats2half2_rn(v0.z, v0.w);
    __half2 h2 = __floats2half2_rn(v1.x, v1.y);
    __half2 h3 = __floats2half2_rn(v1.z, v1.w);
    uint4 u;
    u.x = *reinterpret_cast<uint32_t*>(&h0);
    u.y = *reinterpret_cast<uint32_t*>(&h1);
    u.z = *reinterpret_cast<uint32_t*>(&h2);
    u.w = *reinterpret_cast<uint32_t*>(&h3);
    reinterpret_cast<uint4*>(out)[i] = u;
}

// ---------------- fused weight conversion + bias concat ----------------
__global__ void cvt_all_k(const float* __restrict__ Wq, const float* __restrict__ Wkv,
                          const float* __restrict__ We, const float* __restrict__ Wo,
                          const float* __restrict__ Wf1, const float* __restrict__ Wf2,
                          const float* __restrict__ Wp, float* __restrict__ out,
                          __half* __restrict__ outh,
                          const float* __restrict__ bq, const float* __restrict__ bkv,
                          float* __restrict__ bqkv)
{
    int i = blockIdx.x * blockDim.x + threadIdx.x;
    if (i < DEPTH * 3 * INNER) {
        int d = i / (3 * INNER), c = i % (3 * INNER);
        bqkv[i] = (c < INNER) ? bq[d * INNER + c] : bkv[d * 2 * INNER + (c - INNER)];
    }
    if (i >= WT_TOTAL) return;
    float v;
    if (i < WE_OFF) {
        int t = i;
        int d = t / (DIM * 3 * INNER);
        int r = (t / (3 * INNER)) % DIM;
        int c = t % (3 * INNER);
        v = (c < INNER) ? Wq[((size_t)d * DIM + r) * INNER + c]
                        : Wkv[((size_t)d * DIM + r) * (2 * INNER) + (c - INNER)];
    } else if (i < WO_OFF) v = We[i - WE_OFF];
    else if (i < WF1_OFF) v = Wo[i - WO_OFF];
    else if (i < WF2_OFF) v = Wf1[i - WF1_OFF];
    else if (i < WPROJ_OFF) v = Wf2[i - WF2_OFF];
    else v = Wp[i - WPROJ_OFF];
    out[i] = __uint_as_float(f2tf32(v));
    if (i < WO_OFF) outh[i] = __float2half_rn(v);
    else if (i >= WF1_OFF && i < WPROJ_OFF) outh[i - 131072] = __float2half_rn(v);
}

// ---------------- LayerNorm (fp16 out; first use only) ----------------
__global__ void layernorm_k(const float* __restrict__ x, const float* __restrict__ g,
                            const float* __restrict__ b, __half* __restrict__ out, int n)
{
    int w = (blockIdx.x * blockDim.x + threadIdx.x) >> 5;
    int lane = threadIdx.x & 31;
    if (w >= n) return;
    const float* xp = x + (size_t)w * DIM;
    float v[8], s = 0.f, sq = 0.f;
#pragma unroll
    for (int j = 0; j < 8; j++) {
        v[j] = xp[lane + j * 32];
        s += v[j];
        sq += v[j] * v[j];
    }
#pragma unroll
    for (int o = 16; o; o >>= 1) {
        s += __shfl_xor_sync(0xffffffffu, s, o);
        sq += __shfl_xor_sync(0xffffffffu, sq, o);
    }
    float mean = s * (1.f / DIM);
    float var = sq * (1.f / DIM) - mean * mean;
    float rstd = rsqrtf(var + LNEPS);
#pragma unroll
    for (int j = 0; j < 8; j++) {
        int d = lane + j * 32;
        out[(size_t)w * DIM + d] = __float2half_rn((v[j] - mean) * rstd * g[d] + b[d]);
    }
}

// ---------------- fused gated residual + LayerNorm (fp16 xn out) ----------------
__global__ void gated_ln_k(const float* __restrict__ y, const float* __restrict__ res,
                           const float* __restrict__ gw, const float* __restrict__ lng,
                           const float* __restrict__ lnb, float* __restrict__ xout,
                           __half* __restrict__ xnout, int n)
{
    int w = (blockIdx.x * blockDim.x + threadIdx.x) >> 5;
    int lane = threadIdx.x & 31;
    if (w >= n) return;
    const float* yp = y + (size_t)w * DIM;
    const float* rp = res + (size_t)w * DIM;
    float yv[8], rv[8];
    float s = 0.f;
#pragma unroll
    for (int j = 0; j < 8; j++) {
        int d = lane + j * 32;
        yv[j] = yp[d];
        rv[j] = rp[d];
        s += yv[j] * gw[d] + rv[j] * gw[DIM + d] + (yv[j] - rv[j]) * gw[2 * DIM + d];
    }
#pragma unroll
    for (int o = 16; o; o >>= 1) s += __shfl_xor_sync(0xffffffffu, s, o);
    float gate = 1.f / (1.f + expf(-s));
    float gr[8], sum = 0.f, sq = 0.f;
#pragma unroll
    for (int j = 0; j < 8; j++) {
        gr[j] = yv[j] * gate + rv[j] * (1.f - gate);
        sum += gr[j];
        sq += gr[j] * gr[j];
    }
#pragma unroll
    for (int o = 16; o; o >>= 1) {
        sum += __shfl_xor_sync(0xffffffffu, sum, o);
        sq += __shfl_xor_sync(0xffffffffu, sq, o);
    }
    float mean = sum * (1.f / DIM);
    float var = sq * (1.f / DIM) - mean * mean;
    float rstd = rsqrtf(var + LNEPS);
#pragma unroll
    for (int j = 0; j < 8; j++) {
        int d = lane + j * 32;
        xout[(size_t)w * DIM + d] = gr[j];
        xnout[(size_t)w * DIM + d] = __float2half_rn((gr[j] - mean) * rstd * lng[d] + lnb[d]);
    }
}

// ---------------- plain gated residual (last use only) ----------------
__global__ void gated_residual_k(const float* __restrict__ y, const float* __restrict__ res,
                                 const float* __restrict__ gw, float* __restrict__ xout, int n)
{
    int w = (blockIdx.x * blockDim.x + threadIdx.x) >> 5;
    int lane = threadIdx.x & 31;
    if (w >= n) return;
    const float* yp = y + (size_t)w * DIM;
    const float* rp = res + (size_t)w * DIM;
    float s = 0.f;
#pragma unroll
    for (int j = 0; j < 8; j++) {
        int d = lane + j * 32;
        float yv = yp[d], rv = rp[d];
        s += yv * gw[d] + rv * gw[DIM + d] + (yv - rv) * gw[2 * DIM + d];
    }
#pragma unroll
    for (int o = 16; o; o >>= 1) s += __shfl_xor_sync(0xffffffffu, s, o);
    float gate = 1.f / (1.f + expf(-s));
#pragma unroll
    for (int j = 0; j < 8; j++) {
        int d = lane + j * 32;
        float yv = yp[d], rv = rp[d];
        xout[(size_t)w * DIM + d] = yv * gate + rv * (1.f - gate);
    }
}

// ---------------- fused attention (one pass) + normalize ----------------
__global__ void attn_fused_k(const __half* __restrict__ qkv,
                             const __nv_bfloat16* __restrict__ eb,
                             const int* __restrict__ srcI, const int* __restrict__ dstI,
                             float* __restrict__ den, float* __restrict__ agg, int ne)
{
    int w = (blockIdx.x * blockDim.x + threadIdx.x) >> 5;
    int lane = threadIdx.x & 31;
    if (w >= ne) return;
    int s = srcI[w], d = dstI[w];
    int off = lane * 8;
    uint4 qu = *reinterpret_cast<const uint4*>(qkv + (size_t)d * 768 + off);
    uint4 ku = *reinterpret_cast<const uint4*>(qkv + (size_t)s * 768 + 256 + off);
    uint4 vu = *reinterpret_cast<const uint4*>(qkv + (size_t)s * 768 + 512 + off);
    uint4 eu = *reinterpret_cast<const uint4*>(eb + (size_t)w * INNER + off);
    float2 q0 = h2f2(qu.x), q1 = h2f2(qu.y), q2 = h2f2(qu.z), q3 = h2f2(qu.w);
    float2 k0 = h2f2(ku.x), k1 = h2f2(ku.y), k2 = h2f2(ku.z), k3 = h2f2(ku.w);
    float2 v0 = h2f2(vu.x), v1 = h2f2(vu.y), v2 = h2f2(vu.z), v3 = h2f2(vu.w);
    float2 e0 = bf2f2(eu.x), e1 = bf2f2(eu.y), e2 = bf2f2(eu.z), e3 = bf2f2(eu.w);
    float dot = q0.x * (k0.x + e0.x) + q0.y * (k0.y + e0.y)
              + q1.x * (k1.x + e1.x) + q1.y * (k1.y + e1.y)
              + q2.x * (k2.x + e2.x) + q2.y * (k2.y + e2.y)
              + q3.x * (k3.x + e3.x) + q3.y * (k3.y + e3.y);
    dot += __shfl_xor_sync(0xffffffffu, dot, 1);
    dot += __shfl_xor_sync(0xffffffffu, dot, 2);
    dot += __shfl_xor_sync(0xffffffffu, dot, 4);
    float p = __expf(dot * 0.125f);
    if ((lane & 7) == 0)
        atomicAdd(&den[d * HEADS + (lane >> 3)], p);
    float* base = agg + (size_t)d * INNER + off;
    asm volatile("red.global.add.v4.f32 [%0], {%1,%2,%3,%4};"
                 :: "l"(base), "f"(p * (v0.x + e0.x)), "f"(p * (v0.y + e0.y)),
                    "f"(p * (v1.x + e1.x)), "f"(p * (v1.y + e1.y)) : "memory");
    asm volatile("red.global.add.v4.f32 [%0], {%1,%2,%3,%4};"
                 :: "l"(base + 4), "f"(p * (v2.x + e2.x)), "f"(p * (v2.y + e2.y)),
                    "f"(p * (v3.x + e3.x)), "f"(p * (v3.y + e3.y)) : "memory");
}

__global__ void normalize_agg_k(float* __restrict__ agg, const float* __restrict__ den)
{
    int i = blockIdx.x * blockDim.x + threadIdx.x;
    if (i >= NN * INNER / 4) return;
    int node = i >> 6;
    int head = (i & 63) >> 4;
    float dd = den[node * HEADS + head];
    float inv = (dd > 0.f) ? 1.f / dd : 0.f;
    float4 v = reinterpret_cast<float4*>(agg)[i];
    v.x *= inv; v.y *= inv; v.z *= inv; v.w *= inv;
    reinterpret_cast<float4*>(agg)[i] = v;
}

// ---------------- host side ----------------
static inline dim3 gemm_grid(int M, int N) { return dim3((N + 127) / 128, (M + 127) / 128); }

extern "C" void kernel_launch(void* const* d_in, const int* in_sizes, int n_in,
                              void* d_out, int out_size)
{
    const float* x_in      = (const float*)d_in[0];
    const float* edge_attr = (const float*)d_in[1];
    const int*   edge_idx  = (const int*)d_in[2];
    const float* ln1_g = (const float*)d_in[3];
    const float* ln1_b = (const float*)d_in[4];
    const float* Wq  = (const float*)d_in[5];
    const float* bq  = (const float*)d_in[6];
    const float* Wkv = (const float*)d_in[7];
    const float* bkv = (const float*)d_in[8];
    const float* We  = (const float*)d_in[9];
    const float* be  = (const float*)d_in[10];
    const float* Wo  = (const float*)d_in[11];
    const float* bo  = (const float*)d_in[12];
    const float* gate_attn_W = (const float*)d_in[13];
    const float* ln2_g = (const float*)d_in[14];
    const float* ln2_b = (const float*)d_in[15];
    const float* Wff1 = (const float*)d_in[16];
    const float* bff1 = (const float*)d_in[17];
    const float* Wff2 = (const float*)d_in[18];
    const float* bff2 = (const float*)d_in[19];
    const float* gate_ff_W = (const float*)d_in[20];
    const float* Wproj = (const float*)d_in[21];
    const float* bproj = (const float*)d_in[22];
    float* out = (float*)d_out;

    const int* src = edge_idx;
    const int* dst = edge_idx + EE;

    float *px, *pden, *pagg, *py, *pwt, *pbqkv;
    __half *pxnh, *pqkvh, *peah, *pffh, *pwth;
    __nv_bfloat16 *pe0, *pe1;
    cudaGetSymbolAddress((void**)&px, g_x);
    cudaGetSymbolAddress((void**)&pxnh, g_xnh);
    cudaGetSymbolAddress((void**)&pqkvh, g_qkvh);
    cudaGetSymbolAddress((void**)&peah, g_eah);
    cudaGetSymbolAddress((void**)&pe0, g_e0);
    cudaGetSymbolAddress((void**)&pe1, g_e1);
    cudaGetSymbolAddress((void**)&pden, g_den);
    cudaGetSymbolAddress((void**)&pagg, g_agg);
    cudaGetSymbolAddress((void**)&py, g_y);
    cudaGetSymbolAddress((void**)&pffh, g_ffh);
    cudaGetSymbolAddress((void**)&pwt, g_wt);
    cudaGetSymbolAddress((void**)&pwth, g_wth);
    cudaGetSymbolAddress((void**)&pbqkv, g_bqkv);

    static cudaStream_t s1 = nullptr;
    static cudaEvent_t evW = nullptr, evE0 = nullptr, evE1 = nullptr;
    static bool attr_set = false;
    if (!attr_set) {
        cudaFuncSetAttribute(tgemm_v4, cudaFuncAttributeMaxDynamicSharedMemorySize, SMEM_BYTES);
        cudaFuncSetAttribute(tgemm_h16<0>, cudaFuncAttributeMaxDynamicSharedMemorySize, HSMEM_BYTES);
        cudaFuncSetAttribute(tgemm_h16<1>, cudaFuncAttributeMaxDynamicSharedMemorySize, HSMEM_BYTES);
        cudaFuncSetAttribute(tgemm_h16<2>, cudaFuncAttributeMaxDynamicSharedMemorySize, HSMEM_BYTES);
        cudaFuncSetAttribute(tgemm_h16<3>, cudaFuncAttributeMaxDynamicSharedMemorySize, HSMEM_BYTES);
        cudaStreamCreateWithFlags(&s1, cudaStreamNonBlocking);
        cudaEventCreateWithFlags(&evW, cudaEventDisableTiming);
        cudaEventCreateWithFlags(&evE0, cudaEventDisableTiming);
        cudaEventCreateWithFlags(&evE1, cudaEventDisableTiming);
        attr_set = true;
    }

    const int warpBlocks_N = (NN * 32 + 255) / 256;
    const int warpBlocks_E = (EE * 32 + 255) / 256;

    // ---- main stream: weights + fork point ----
    cudaMemcpyAsync(px, x_in, (size_t)NN * DIM * sizeof(float), cudaMemcpyDeviceToDevice, 0);
    cvt_all_k<<<(WT_TOTAL + 255) / 256, 256>>>(Wq, Wkv, We, Wo, Wff1, Wff2, Wproj, pwt, pwth,
                                               bq, bkv, pbqkv);
    cudaEventRecord(evW, 0);

    // ---- side stream: edge pipeline (cvt_ea -> edge GEMM d0 -> edge GEMM d1) ----
    cudaStreamWaitEvent(s1, evW, 0);
    {
        size_t n8 = (size_t)EE * EDIM / 8;
        cvt_ea_k<<<(unsigned)((n8 + 255) / 256), 256, 0, s1>>>(edge_attr, peah);
    }
    tgemm_h16<2><<<gemm_grid(EE, INNER), 128, HSMEM_BYTES, s1>>>(
        peah, pwth + 393216, be, pe0, EE, INNER, EDIM);
    cudaEventRecord(evE0, s1);
    tgemm_h16<2><<<gemm_grid(EE, INNER), 128, HSMEM_BYTES, s1>>>(
        peah, pwth + 393216 + (size_t)EDIM * INNER, be + INNER, pe1, EE, INNER, EDIM);
    cudaEventRecord(evE1, s1);

    // ---- main stream: node pipeline ----
    layernorm_k<<<warpBlocks_N, 256>>>(px, ln1_g, ln1_b, pxnh, NN);

    __nv_bfloat16* peL[2] = {pe0, pe1};
    cudaEvent_t evL[2] = {evE0, evE1};

    for (int d = 0; d < DEPTH; d++) {
        const __half* wqkvh = pwth + (size_t)d * DIM * 3 * INNER;
        const __half* wf1h  = pwth + 655360 + (size_t)d * DIM * FF;
        const __half* wf2h  = pwth + 1179648 + (size_t)d * FF * DIM;
        const float* wo  = pwt + WO_OFF + (size_t)d * INNER * DIM;
        const float* bod = bo + d * DIM;
        const float* gaw = gate_attn_W + (size_t)d * 3 * DIM;
        const float* l2g = ln2_g + d * DIM;
        const float* l2b = ln2_b + d * DIM;
        const float* bf1 = bff1 + d * FF;
        const float* bf2 = bff2 + d * DIM;
        const float* gfw = gate_ff_W + (size_t)d * 3 * DIM;

        tgemm_h16<3><<<gemm_grid(NN, 3 * INNER), 128, HSMEM_BYTES>>>(
            pxnh, wqkvh, pbqkv + d * 768, pqkvh, NN, 3 * INNER, DIM);

        cudaMemsetAsync(pden, 0, (size_t)NN * HEADS * sizeof(float), 0);
        cudaMemsetAsync(pagg, 0, (size_t)NN * INNER * sizeof(float), 0);
        cudaStreamWaitEvent(0, evL[d], 0);   // join: edge GEMM for this layer done
        attn_fused_k<<<warpBlocks_E, 256>>>(pqkvh, peL[d], src, dst, pden, pagg, EE);
        normalize_agg_k<<<(NN * INNER / 4 + 255) / 256, 256>>>(pagg, pden);

        tgemm_v4<<<gemm_grid(NN, DIM), 128, SMEM_BYTES>>>(pagg, wo, bod, py, NN, DIM, INNER);
        gated_ln_k<<<warpBlocks_N, 256>>>(py, px, gaw, l2g, l2b, px, pxnh, NN);

        tgemm_h16<1><<<gemm_grid(NN, FF), 128, HSMEM_BYTES>>>(
            pxnh, wf1h, bf1, pffh, NN, FF, DIM);
        tgemm_h16<0><<<gemm_grid(NN, DIM), 128, HSMEM_BYTES>>>(
            pffh, wf2h, bf2, py, NN, DIM, FF);

        if (d + 1 < DEPTH) {
            gated_ln_k<<<warpBlocks_N, 256>>>(py, px, gfw,
                                              ln1_g + (d + 1) * DIM, ln1_b + (d + 1) * DIM,
                                              px, pxnh, NN);
        } else {
            gated_residual_k<<<warpBlocks_N, 256>>>(py, px, gfw, px, NN);
        }
    }

    tgemm_v4<<<gemm_grid(NN, OUTD), 128, SMEM_BYTES>>>(px, pwt + WPROJ_OFF, bproj, out, NN, OUTD, DIM);
}

// round 16
// speedup vs baseline: 1.1496x; 1.0012x over previous
#include <cuda_runtime.h>
#include <cuda_bf16.h>
#include <cuda_fp16.h>
#include <cstdint>

// ---------------- problem constants ----------------
#define NN 20000
#define EE 200000
#define DIM 256
#define HEADS 4
#define DH 64
#define INNER 256
#define EDIM 512
#define FF 1024
#define OUTD 128
#define DEPTH 2
#define LNEPS 1e-5f

// ---------------- scratch (device globals; no allocation allowed) ----------------
__device__ float g_x[NN * DIM];
__device__ __half g_xnh[NN * DIM];
__device__ __half g_qkvh[NN * 3 * INNER];
__device__ __half g_eah[(size_t)EE * EDIM];
__device__ __nv_bfloat16 g_e0[(size_t)EE * INNER];    // layer-0 edge projections
__device__ __nv_bfloat16 g_e1[(size_t)EE * INNER];    // layer-1 edge projections
__device__ float g_den[NN * HEADS];
__device__ float g_agg[NN * INNER];
__device__ float g_y[NN * DIM];
__device__ __half g_ffh[NN * FF];
__device__ float g_bqkv[DEPTH * 3 * INNER];
// tf32 weights (wo, proj)
#define WQKV_OFF  0
#define WE_OFF    393216
#define WO_OFF    655360
#define WF1_OFF   786432
#define WF2_OFF   1310720
#define WPROJ_OFF 1835008
#define WT_TOTAL  1867776
__device__ float g_wt[WT_TOTAL];
// fp16 weights (qkv, we, ff1, ff2)
#define WTH_TOTAL 1703936
__device__ __half g_wth[WTH_TOTAL];

// ---------------- helpers ----------------
__device__ __forceinline__ uint32_t f2tf32(float f)
{
    uint32_t r;
    asm("cvt.rna.tf32.f32 %0, %1;" : "=r"(r) : "f"(f));
    return r;
}

__device__ __forceinline__ void mma_tf32(float* c, const uint32_t* a, const uint32_t* b)
{
    asm volatile(
        "mma.sync.aligned.m16n8k8.row.col.f32.tf32.tf32.f32 "
        "{%0,%1,%2,%3}, {%4,%5,%6,%7}, {%8,%9}, {%0,%1,%2,%3};"
        : "+f"(c[0]), "+f"(c[1]), "+f"(c[2]), "+f"(c[3])
        : "r"(a[0]), "r"(a[1]), "r"(a[2]), "r"(a[3]), "r"(b[0]), "r"(b[1]));
}

__device__ __forceinline__ void mma_f16(float* c, const uint32_t* a, const uint32_t* b)
{
    asm volatile(
        "mma.sync.aligned.m16n8k16.row.col.f32.f16.f16.f32 "
        "{%0,%1,%2,%3}, {%4,%5,%6,%7}, {%8,%9}, {%0,%1,%2,%3};"
        : "+f"(c[0]), "+f"(c[1]), "+f"(c[2]), "+f"(c[3])
        : "r"(a[0]), "r"(a[1]), "r"(a[2]), "r"(a[3]), "r"(b[0]), "r"(b[1]));
}

__device__ __forceinline__ uint32_t smem_u32(const void* p)
{
    return (uint32_t)__cvta_generic_to_shared(p);
}

__device__ __forceinline__ float2 bf2f2(uint32_t u)
{
    __nv_bfloat162 h = *reinterpret_cast<__nv_bfloat162*>(&u);
    return __bfloat1622float2(h);
}

__device__ __forceinline__ float2 h2f2(uint32_t u)
{
    __half2 h = *reinterpret_cast<__half2*>(&u);
    return __half22float2(h);
}

__device__ __forceinline__ float gelu_f(float v)
{
    float c3 = v * v * v;
    return 0.5f * v * (1.f + tanhf(0.7978845608028654f * (v + 0.044715f * c3)));
}

// ---------------- TF32 GEMM v4 (wo + proj) ----------------
#define AS_STRIDE 36
#define BS_STRIDE 136
#define STAGE_WORDS (128 * AS_STRIDE + 32 * BS_STRIDE)
#define SMEM_WORDS (3 * STAGE_WORDS)
#define SMEM_BYTES (SMEM_WORDS * 4)

__global__ __launch_bounds__(128, 2) void tgemm_v4(
    const float* __restrict__ A, const float* __restrict__ B,
    const float* __restrict__ bias, float* __restrict__ C,
    int M, int N, int K)
{
    extern __shared__ uint32_t smem[];
    const int tid = threadIdx.x;
    const int warp = tid >> 5, lane = tid & 31;
    const int warpM = warp >> 1, warpN = warp & 1;
    const int g = lane >> 2, tg = lane & 3;
    const int row0 = blockIdx.y * 128, col0 = blockIdx.x * 128;
    const int lm_row = (lane & 7) + ((lane >> 3) & 1) * 8;
    const int lm_col = (lane >> 4) * 4;

    float acc[4][8][4];
#pragma unroll
    for (int i = 0; i < 4; i++)
#pragma unroll
        for (int j = 0; j < 8; j++)
#pragma unroll
            for (int r = 0; r < 4; r++) acc[i][j][r] = 0.f;

    auto stage = [&](int buf, int k0) {
        uint32_t* As = smem + (size_t)buf * STAGE_WORDS;
        uint32_t* Bs = As + 128 * AS_STRIDE;
#pragma unroll
        for (int i = 0; i < 8; i++) {
            int c = tid + 128 * i;
            int r = c >> 3, cc = (c & 7) * 4;
            int grow = row0 + r;
            int sz = (grow < M) ? 16 : 0;
            if (grow >= M) grow = M - 1;
            const float* src = A + (size_t)grow * K + k0 + cc;
            uint32_t dstp = smem_u32(&As[r * AS_STRIDE + cc]);
            asm volatile("cp.async.cg.shared.global [%0], [%1], 16, %2;"
                         :: "r"(dstp), "l"(src), "r"(sz));
        }
#pragma unroll
        for (int i = 0; i < 8; i++) {
            int c = tid + 128 * i;
            int r = c >> 5, cc = (c & 31) * 4;
            const float* src = B + (size_t)(k0 + r) * N + col0 + cc;
            uint32_t dstp = smem_u32(&Bs[r * BS_STRIDE + cc]);
            asm volatile("cp.async.cg.shared.global [%0], [%1], 16, 16;"
                         :: "r"(dstp), "l"(src));
        }
        asm volatile("cp.async.commit_group;");
    };

    const int nk = K >> 5;
    stage(0, 0);
    stage(1, 32);

    int buf = 0;
    for (int t = 0; t < nk; t++) {
        if (t + 2 < nk) stage((t + 2) % 3, (t + 2) * 32);
        int rem = nk - 1 - t;
        if (rem >= 2)      asm volatile("cp.async.wait_group 2;");
        else if (rem == 1) asm volatile("cp.async.wait_group 1;");
        else               asm volatile("cp.async.wait_group 0;");
        __syncthreads();

        const uint32_t* Ab = smem + (size_t)buf * STAGE_WORDS;
        const uint32_t* Bb = Ab + 128 * AS_STRIDE;

#pragma unroll
        for (int ks = 0; ks < 4; ks++) {
            const int kk = ks * 8;
            uint32_t a[4][4], b[8][2];
#pragma unroll
            for (int mf = 0; mf < 4; mf++) {
                int m0 = warpM * 64 + mf * 16;
                uint32_t addr = smem_u32(&Ab[(m0 + lm_row) * AS_STRIDE + kk + lm_col]);
                asm volatile("ldmatrix.sync.aligned.m8n8.x4.shared.b16 {%0,%1,%2,%3}, [%4];"
                             : "=r"(a[mf][0]), "=r"(a[mf][1]), "=r"(a[mf][2]), "=r"(a[mf][3])
                             : "r"(addr));
            }
#pragma unroll
            for (int nf = 0; nf < 8; nf++) {
                int n = warpN * 64 + nf * 8 + g;
                b[nf][0] = Bb[(kk + tg) * BS_STRIDE + n];
                b[nf][1] = Bb[(kk + tg + 4) * BS_STRIDE + n];
            }
#pragma unroll
            for (int mf = 0; mf < 4; mf++)
#pragma unroll
                for (int nf = 0; nf < 8; nf++)
                    mma_tf32(acc[mf][nf], a[mf], b[nf]);
        }
        __syncthreads();
        buf = (buf + 1) % 3;
    }

#pragma unroll
    for (int mf = 0; mf < 4; mf++) {
#pragma unroll
        for (int half = 0; half < 2; half++) {
            int row = row0 + warpM * 64 + mf * 16 + g + half * 8;
            if (row >= M) continue;
#pragma unroll
            for (int nf = 0; nf < 8; nf++) {
                int col = col0 + warpN * 64 + nf * 8 + 2 * tg;
                float v0 = acc[mf][nf][half * 2 + 0] + bias[col];
                float v1 = acc[mf][nf][half * 2 + 1] + bias[col + 1];
                *reinterpret_cast<float2*>(C + (size_t)row * N + col) = make_float2(v0, v1);
            }
        }
    }
}

// ---------------- FP16 GEMM (128 thr, 4 warps 2x2, warp tile 64x64) ----------------
#define HA_STRIDE 40
#define HB_STRIDE 136
#define HSTAGE (128 * HA_STRIDE + 32 * HB_STRIDE)
#define HSMEM_BYTES (3 * HSTAGE * 2)

template <int EPI>
__global__ __launch_bounds__(128, 2) void tgemm_h16(
    const __half* __restrict__ A, const __half* __restrict__ B,
    const float* __restrict__ bias, void* __restrict__ C,
    int M, int N, int K)
{
    extern __shared__ __half hsmem[];
    const int tid = threadIdx.x;
    const int warp = tid >> 5, lane = tid & 31;
    const int warpM = warp >> 1, warpN = warp & 1;
    const int g = lane >> 2, tg = lane & 3;
    const int row0 = blockIdx.y * 128, col0 = blockIdx.x * 128;
    const int lm_row = (lane & 7) + ((lane >> 3) & 1) * 8;
    const int lm_col = (lane >> 4) * 8;

    float acc[4][8][4];
#pragma unroll
    for (int i = 0; i < 4; i++)
#pragma unroll
        for (int j = 0; j < 8; j++)
#pragma unroll
            for (int r = 0; r < 4; r++) acc[i][j][r] = 0.f;

    auto stage = [&](int buf, int k0) {
        __half* As = hsmem + (size_t)buf * HSTAGE;
        __half* Bs = As + 128 * HA_STRIDE;
#pragma unroll
        for (int i = 0; i < 4; i++) {
            int c = tid + 128 * i;
            int r = c >> 2, cc = (c & 3) * 8;
            int grow = row0 + r;
            int sz = (grow < M) ? 16 : 0;
            if (grow >= M) grow = M - 1;
            const __half* src = A + (size_t)grow * K + k0 + cc;
            uint32_t dstp = smem_u32(&As[r * HA_STRIDE + cc]);
            asm volatile("cp.async.cg.shared.global [%0], [%1], 16, %2;"
                         :: "r"(dstp), "l"(src), "r"(sz));
        }
#pragma unroll
        for (int i = 0; i < 4; i++) {
            int c = tid + 128 * i;
            int r = c >> 4, cc = (c & 15) * 8;
            const __half* src = B + (size_t)(k0 + r) * N + col0 + cc;
            uint32_t dstp = smem_u32(&Bs[r * HB_STRIDE + cc]);
            asm volatile("cp.async.cg.shared.global [%0], [%1], 16, 16;"
                         :: "r"(dstp), "l"(src));
        }
        asm volatile("cp.async.commit_group;");
    };

    const int nk = K >> 5;
    stage(0, 0);
    stage(1, 32);

    int buf = 0;
    for (int t = 0; t < nk; t++) {
        if (t + 2 < nk) stage((t + 2) % 3, (t + 2) * 32);
        int rem = nk - 1 - t;
        if (rem >= 2)      asm volatile("cp.async.wait_group 2;");
        else if (rem == 1) asm volatile("cp.async.wait_group 1;");
        else               asm volatile("cp.async.wait_group 0;");
        __syncthreads();

        const __half* Ab = hsmem + (size_t)buf * HSTAGE;
        const __half* Bb = Ab + 128 * HA_STRIDE;

#pragma unroll
        for (int ks = 0; ks < 2; ks++) {
            const int kk = ks * 16;
            uint32_t a[4][4], b[8][2];
#pragma unroll
            for (int mf = 0; mf < 4; mf++) {
                int m0 = warpM * 64 + mf * 16;
                uint32_t addr = smem_u32(&Ab[(m0 + lm_row) * HA_STRIDE + kk + lm_col]);
                asm volatile("ldmatrix.sync.aligned.m8n8.x4.shared.b16 {%0,%1,%2,%3}, [%4];"
                             : "=r"(a[mf][0]), "=r"(a[mf][1]), "=r"(a[mf][2]), "=r"(a[mf][3])
                             : "r"(addr));
            }
#pragma unroll
            for (int nf2 = 0; nf2 < 4; nf2++) {
                int n0 = warpN * 64 + nf2 * 16;
                int brow = kk + (lane & 7) + ((lane >> 3) & 1) * 8;
                int bcol = n0 + (lane >> 4) * 8;
                uint32_t addr = smem_u32(&Bb[brow * HB_STRIDE + bcol]);
                asm volatile("ldmatrix.sync.aligned.m8n8.x4.trans.shared.b16 {%0,%1,%2,%3}, [%4];"
                             : "=r"(b[2 * nf2][0]), "=r"(b[2 * nf2][1]),
                               "=r"(b[2 * nf2 + 1][0]), "=r"(b[2 * nf2 + 1][1])
                             : "r"(addr));
            }
#pragma unroll
            for (int mf = 0; mf < 4; mf++)
#pragma unroll
                for (int nf = 0; nf < 8; nf++)
                    mma_f16(acc[mf][nf], a[mf], b[nf]);
        }
        __syncthreads();
        buf = (buf + 1) % 3;
    }

#pragma unroll
    for (int mf = 0; mf < 4; mf++) {
#pragma unroll
        for (int half = 0; half < 2; half++) {
            int row = row0 + warpM * 64 + mf * 16 + g + half * 8;
            if (row >= M) continue;
#pragma unroll
            for (int nf = 0; nf < 8; nf++) {
                int col = col0 + warpN * 64 + nf * 8 + 2 * tg;
                float v0 = acc[mf][nf][half * 2 + 0] + bias[col];
                float v1 = acc[mf][nf][half * 2 + 1] + bias[col + 1];
                if (EPI == 0) {
                    *reinterpret_cast<float2*>(
                        reinterpret_cast<float*>(C) + (size_t)row * N + col) = make_float2(v0, v1);
                } else if (EPI == 1) {
                    v0 = gelu_f(v0);
                    v1 = gelu_f(v1);
                    __half2 h = __floats2half2_rn(v0, v1);
                    *reinterpret_cast<__half2*>(
                        reinterpret_cast<__half*>(C) + (size_t)row * N + col) = h;
                } else if (EPI == 2) {
                    __nv_bfloat162 h = __floats2bfloat162_rn(v0, v1);
                    *reinterpret_cast<__nv_bfloat162*>(
                        reinterpret_cast<__nv_bfloat16*>(C) + (size_t)row * N + col) = h;
                } else {
                    __half2 h = __floats2half2_rn(v0, v1);
                    *reinterpret_cast<__half2*>(
                        reinterpret_cast<__half*>(C) + (size_t)row * N + col) = h;
                }
            }
        }
    }
}

// ---------------- edge_attr fp32 -> fp16 ----------------
__global__ void cvt_ea_k(const float* __restrict__ in, __half* __restrict__ out)
{
    size_t i = (size_t)blockIdx.x * blockDim.x + threadIdx.x;
    size_t n8 = (size_t)EE * EDIM / 8;
    if (i >= n8) return;
    const float4* p = reinterpret_cast<const float4*>(in) + i * 2;
    float4 v0 = p[0], v1 = p[1];
    __half2 h0 = __floats2half2_rn(v0.x, v0.y);
    __half2 h1 = __floats2half2_rn(v0.z, v0.w);
    __half2 h2 = __floats2half2_rn(v1.x, v1.y);
    __half2 h3 = __floats2half2_rn(v1.z, v1.w);
    uint4 u;
    u.x = *reinterpret_cast<uint32_t*>(&h0);
    u.y = *reinterpret_cast<uint32_t*>(&h1);
    u.z = *reinterpret_cast<uint32_t*>(&h2);
    u.w = *reinterpret_cast<uint32_t*>(&h3);
    reinterpret_cast<uint4*>(out)[i] = u;
}

// ---------------- fused weight conversion + bias concat ----------------
__global__ void cvt_all_k(const float* __restrict__ Wq, const float* __restrict__ Wkv,
                          const float* __restrict__ We, const float* __restrict__ Wo,
                          const float* __restrict__ Wf1, const float* __restrict__ Wf2,
                          const float* __restrict__ Wp, float* __restrict__ out,
                          __half* __restrict__ outh,
                          const float* __restrict__ bq, const float* __restrict__ bkv,
                          float* __restrict__ bqkv)
{
    int i = blockIdx.x * blockDim.x + threadIdx.x;
    if (i < DEPTH * 3 * INNER) {
        int d = i / (3 * INNER), c = i % (3 * INNER);
        bqkv[i] = (c < INNER) ? bq[d * INNER + c] : bkv[d * 2 * INNER + (c - INNER)];
    }
    if (i >= WT_TOTAL) return;
    float v;
    if (i < WE_OFF) {
        int t = i;
        int d = t / (DIM * 3 * INNER);
        int r = (t / (3 * INNER)) % DIM;
        int c = t % (3 * INNER);
        v = (c < INNER) ? Wq[((size_t)d * DIM + r) * INNER + c]
                        : Wkv[((size_t)d * DIM + r) * (2 * INNER) + (c - INNER)];
    } else if (i < WO_OFF) v = We[i - WE_OFF];
    else if (i < WF1_OFF) v = Wo[i - WO_OFF];
    else if (i < WF2_OFF) v = Wf1[i - WF1_OFF];
    else if (i < WPROJ_OFF) v = Wf2[i - WF2_OFF];
    else v = Wp[i - WPROJ_OFF];
    out[i] = __uint_as_float(f2tf32(v));
    if (i < WO_OFF) outh[i] = __float2half_rn(v);
    else if (i >= WF1_OFF && i < WPROJ_OFF) outh[i - 131072] = __float2half_rn(v);
}

// ---------------- LayerNorm (fp16 out; first use only) ----------------
__global__ void layernorm_k(const float* __restrict__ x, const float* __restrict__ g,
                            const float* __restrict__ b, __half* __restrict__ out, int n)
{
    int w = (blockIdx.x * blockDim.x + threadIdx.x) >> 5;
    int lane = threadIdx.x & 31;
    if (w >= n) return;
    const float* xp = x + (size_t)w * DIM;
    float v[8], s = 0.f, sq = 0.f;
#pragma unroll
    for (int j = 0; j < 8; j++) {
        v[j] = xp[lane + j * 32];
        s += v[j];
        sq += v[j] * v[j];
    }
#pragma unroll
    for (int o = 16; o; o >>= 1) {
        s += __shfl_xor_sync(0xffffffffu, s, o);
        sq += __shfl_xor_sync(0xffffffffu, sq, o);
    }
    float mean = s * (1.f / DIM);
    float var = sq * (1.f / DIM) - mean * mean;
    float rstd = rsqrtf(var + LNEPS);
#pragma unroll
    for (int j = 0; j < 8; j++) {
        int d = lane + j * 32;
        out[(size_t)w * DIM + d] = __float2half_rn((v[j] - mean) * rstd * g[d] + b[d]);
    }
}

// ---------------- fused gated residual + LayerNorm (fp16 xn out) ----------------
__global__ void gated_ln_k(const float* __restrict__ y, const float* __restrict__ res,
                           const float* __restrict__ gw, const float* __restrict__ lng,
                           const float* __restrict__ lnb, float* __restrict__ xout,
                           __half* __restrict__ xnout, int n)
{
    int w = (blockIdx.x * blockDim.x + threadIdx.x) >> 5;
    int lane = threadIdx.x & 31;
    if (w >= n) return;
    const float* yp = y + (size_t)w * DIM;
    const float* rp = res + (size_t)w * DIM;
    float yv[8], rv[8];
    float s = 0.f;
#pragma unroll
    for (int j = 0; j < 8; j++) {
        int d = lane + j * 32;
        yv[j] = yp[d];
        rv[j] = rp[d];
        s += yv[j] * gw[d] + rv[j] * gw[DIM + d] + (yv[j] - rv[j]) * gw[2 * DIM + d];
    }
#pragma unroll
    for (int o = 16; o; o >>= 1) s += __shfl_xor_sync(0xffffffffu, s, o);
    float gate = 1.f / (1.f + expf(-s));
    float gr[8], sum = 0.f, sq = 0.f;
#pragma unroll
    for (int j = 0; j < 8; j++) {
        gr[j] = yv[j] * gate + rv[j] * (1.f - gate);
        sum += gr[j];
        sq += gr[j] * gr[j];
    }
#pragma unroll
    for (int o = 16; o; o >>= 1) {
        sum += __shfl_xor_sync(0xffffffffu, sum, o);
        sq += __shfl_xor_sync(0xffffffffu, sq, o);
    }
    float mean = sum * (1.f / DIM);
    float var = sq * (1.f / DIM) - mean * mean;
    float rstd = rsqrtf(var + LNEPS);
#pragma unroll
    for (int j = 0; j < 8; j++) {
        int d = lane + j * 32;
        xout[(size_t)w * DIM + d] = gr[j];
        xnout[(size_t)w * DIM + d] = __float2half_rn((gr[j] - mean) * rstd * lng[d] + lnb[d]);
    }
}

// ---------------- plain gated residual (last use only) ----------------
__global__ void gated_residual_k(const float* __restrict__ y, const float* __restrict__ res,
                                 const float* __restrict__ gw, float* __restrict__ xout, int n)
{
    int w = (blockIdx.x * blockDim.x + threadIdx.x) >> 5;
    int lane = threadIdx.x & 31;
    if (w >= n) return;
    const float* yp = y + (size_t)w * DIM;
    const float* rp = res + (size_t)w * DIM;
    float s = 0.f;
#pragma unroll
    for (int j = 0; j < 8; j++) {
        int d = lane + j * 32;
        float yv = yp[d], rv = rp[d];
        s += yv * gw[d] + rv * gw[DIM + d] + (yv - rv) * gw[2 * DIM + d];
    }
#pragma unroll
    for (int o = 16; o; o >>= 1) s += __shfl_xor_sync(0xffffffffu, s, o);
    float gate = 1.f / (1.f + expf(-s));
#pragma unroll
    for (int j = 0; j < 8; j++) {
        int d = lane + j * 32;
        float yv = yp[d], rv = rp[d];
        xout[(size_t)w * DIM + d] = yv * gate + rv * (1.f - gate);
    }
}

// ---------------- fused attention (one pass) + normalize ----------------
__global__ void attn_fused_k(const __half* __restrict__ qkv,
                             const __nv_bfloat16* __restrict__ eb,
                             const int* __restrict__ srcI, const int* __restrict__ dstI,
                             float* __restrict__ den, float* __restrict__ agg, int ne)
{
    int w = (blockIdx.x * blockDim.x + threadIdx.x) >> 5;
    int lane = threadIdx.x & 31;
    if (w >= ne) return;
    int s = srcI[w], d = dstI[w];
    int off = lane * 8;
    uint4 qu = *reinterpret_cast<const uint4*>(qkv + (size_t)d * 768 + off);
    uint4 ku = *reinterpret_cast<const uint4*>(qkv + (size_t)s * 768 + 256 + off);
    uint4 vu = *reinterpret_cast<const uint4*>(qkv + (size_t)s * 768 + 512 + off);
    uint4 eu = *reinterpret_cast<const uint4*>(eb + (size_t)w * INNER + off);
    float2 q0 = h2f2(qu.x), q1 = h2f2(qu.y), q2 = h2f2(qu.z), q3 = h2f2(qu.w);
    float2 k0 = h2f2(ku.x), k1 = h2f2(ku.y), k2 = h2f2(ku.z), k3 = h2f2(ku.w);
    float2 v0 = h2f2(vu.x), v1 = h2f2(vu.y), v2 = h2f2(vu.z), v3 = h2f2(vu.w);
    float2 e0 = bf2f2(eu.x), e1 = bf2f2(eu.y), e2 = bf2f2(eu.z), e3 = bf2f2(eu.w);
    float dot = q0.x * (k0.x + e0.x) + q0.y * (k0.y + e0.y)
              + q1.x * (k1.x + e1.x) + q1.y * (k1.y + e1.y)
              + q2.x * (k2.x + e2.x) + q2.y * (k2.y + e2.y)
              + q3.x * (k3.x + e3.x) + q3.y * (k3.y + e3.y);
    dot += __shfl_xor_sync(0xffffffffu, dot, 1);
    dot += __shfl_xor_sync(0xffffffffu, dot, 2);
    dot += __shfl_xor_sync(0xffffffffu, dot, 4);
    float p = __expf(dot * 0.125f);
    if ((lane & 7) == 0)
        atomicAdd(&den[d * HEADS + (lane >> 3)], p);
    float* base = agg + (size_t)d * INNER + off;
    asm volatile("red.global.add.v4.f32 [%0], {%1,%2,%3,%4};"
                 :: "l"(base), "f"(p * (v0.x + e0.x)), "f"(p * (v0.y + e0.y)),
                    "f"(p * (v1.x + e1.x)), "f"(p * (v1.y + e1.y)) : "memory");
    asm volatile("red.global.add.v4.f32 [%0], {%1,%2,%3,%4};"
                 :: "l"(base + 4), "f"(p * (v2.x + e2.x)), "f"(p * (v2.y + e2.y)),
                    "f"(p * (v3.x + e3.x)), "f"(p * (v3.y + e3.y)) : "memory");
}

__global__ void normalize_agg_k(float* __restrict__ agg, const float* __restrict__ den)
{
    int i = blockIdx.x * blockDim.x + threadIdx.x;
    if (i >= NN * INNER / 4) return;
    int node = i >> 6;
    int head = (i & 63) >> 4;
    float dd = den[node * HEADS + head];
    float inv = (dd > 0.f) ? 1.f / dd : 0.f;
    float4 v = reinterpret_cast<float4*>(agg)[i];
    v.x *= inv; v.y *= inv; v.z *= inv; v.w *= inv;
    reinterpret_cast<float4*>(agg)[i] = v;
}

// ---------------- host side ----------------
static inline dim3 gemm_grid(int M, int N) { return dim3((N + 127) / 128, (M + 127) / 128); }

extern "C" void kernel_launch(void* const* d_in, const int* in_sizes, int n_in,
                              void* d_out, int out_size)
{
    const float* x_in      = (const float*)d_in[0];
    const float* edge_attr = (const float*)d_in[1];
    const int*   edge_idx  = (const int*)d_in[2];
    const float* ln1_g = (const float*)d_in[3];
    const float* ln1_b = (const float*)d_in[4];
    const float* Wq  = (const float*)d_in[5];
    const float* bq  = (const float*)d_in[6];
    const float* Wkv = (const float*)d_in[7];
    const float* bkv = (const float*)d_in[8];
    const float* We  = (const float*)d_in[9];
    const float* be  = (const float*)d_in[10];
    const float* Wo  = (const float*)d_in[11];
    const float* bo  = (const float*)d_in[12];
    const float* gate_attn_W = (const float*)d_in[13];
    const float* ln2_g = (const float*)d_in[14];
    const float* ln2_b = (const float*)d_in[15];
    const float* Wff1 = (const float*)d_in[16];
    const float* bff1 = (const float*)d_in[17];
    const float* Wff2 = (const float*)d_in[18];
    const float* bff2 = (const float*)d_in[19];
    const float* gate_ff_W = (const float*)d_in[20];
    const float* Wproj = (const float*)d_in[21];
    const float* bproj = (const float*)d_in[22];
    float* out = (float*)d_out;

    const int* src = edge_idx;
    const int* dst = edge_idx + EE;

    float *px, *pden, *pagg, *py, *pwt, *pbqkv;
    __half *pxnh, *pqkvh, *peah, *pffh, *pwth;
    __nv_bfloat16 *pe0, *pe1;
    cudaGetSymbolAddress((void**)&px, g_x);
    cudaGetSymbolAddress((void**)&pxnh, g_xnh);
    cudaGetSymbolAddress((void**)&pqkvh, g_qkvh);
    cudaGetSymbolAddress((void**)&peah, g_eah);
    cudaGetSymbolAddress((void**)&pe0, g_e0);
    cudaGetSymbolAddress((void**)&pe1, g_e1);
    cudaGetSymbolAddress((void**)&pden, g_den);
    cudaGetSymbolAddress((void**)&pagg, g_agg);
    cudaGetSymbolAddress((void**)&py, g_y);
    cudaGetSymbolAddress((void**)&pffh, g_ffh);
    cudaGetSymbolAddress((void**)&pwt, g_wt);
    cudaGetSymbolAddress((void**)&pwth, g_wth);
    cudaGetSymbolAddress((void**)&pbqkv, g_bqkv);

    static cudaStream_t s1 = nullptr;
    static cudaEvent_t evW = nullptr, evE0 = nullptr, evE1 = nullptr;
    static bool attr_set = false;
    if (!attr_set) {
        cudaFuncSetAttribute(tgemm_v4, cudaFuncAttributeMaxDynamicSharedMemorySize, SMEM_BYTES);
        cudaFuncSetAttribute(tgemm_h16<0>, cudaFuncAttributeMaxDynamicSharedMemorySize, HSMEM_BYTES);
        cudaFuncSetAttribute(tgemm_h16<1>, cudaFuncAttributeMaxDynamicSharedMemorySize, HSMEM_BYTES);
        cudaFuncSetAttribute(tgemm_h16<2>, cudaFuncAttributeMaxDynamicSharedMemorySize, HSMEM_BYTES);
        cudaFuncSetAttribute(tgemm_h16<3>, cudaFuncAttributeMaxDynamicSharedMemorySize, HSMEM_BYTES);
        cudaStreamCreateWithFlags(&s1, cudaStreamNonBlocking);
        cudaEventCreateWithFlags(&evW, cudaEventDisableTiming);
        cudaEventCreateWithFlags(&evE0, cudaEventDisableTiming);
        cudaEventCreateWithFlags(&evE1, cudaEventDisableTiming);
        attr_set = true;
    }

    const int warpBlocks_N = (NN * 32 + 255) / 256;
    const int warpBlocks_E = (EE * 32 + 255) / 256;

    // ---- main stream: weights + fork point ----
    cudaMemcpyAsync(px, x_in, (size_t)NN * DIM * sizeof(float), cudaMemcpyDeviceToDevice, 0);
    cvt_all_k<<<(WT_TOTAL + 255) / 256, 256>>>(Wq, Wkv, We, Wo, Wff1, Wff2, Wproj, pwt, pwth,
                                               bq, bkv, pbqkv);
    cudaEventRecord(evW, 0);

    // ---- side stream: edge pipeline (cvt_ea -> edge GEMM d0 -> edge GEMM d1) ----
    cudaStreamWaitEvent(s1, evW, 0);
    {
        size_t n8 = (size_t)EE * EDIM / 8;
        cvt_ea_k<<<(unsigned)((n8 + 255) / 256), 256, 0, s1>>>(edge_attr, peah);
    }
    tgemm_h16<2><<<gemm_grid(EE, INNER), 128, HSMEM_BYTES, s1>>>(
        peah, pwth + 393216, be, pe0, EE, INNER, EDIM);
    cudaEventRecord(evE0, s1);
    tgemm_h16<2><<<gemm_grid(EE, INNER), 128, HSMEM_BYTES, s1>>>(
        peah, pwth + 393216 + (size_t)EDIM * INNER, be + INNER, pe1, EE, INNER, EDIM);
    cudaEventRecord(evE1, s1);

    // ---- main stream: node pipeline ----
    layernorm_k<<<warpBlocks_N, 256>>>(px, ln1_g, ln1_b, pxnh, NN);

    __nv_bfloat16* peL[2] = {pe0, pe1};
    cudaEvent_t evL[2] = {evE0, evE1};

    for (int d = 0; d < DEPTH; d++) {
        const __half* wqkvh = pwth + (size_t)d * DIM * 3 * INNER;
        const __half* wf1h  = pwth + 655360 + (size_t)d * DIM * FF;
        const __half* wf2h  = pwth + 1179648 + (size_t)d * FF * DIM;
        const float* wo  = pwt + WO_OFF + (size_t)d * INNER * DIM;
        const float* bod = bo + d * DIM;
        const float* gaw = gate_attn_W + (size_t)d * 3 * DIM;
        const float* l2g = ln2_g + d * DIM;
        const float* l2b = ln2_b + d * DIM;
        const float* bf1 = bff1 + d * FF;
        const float* bf2 = bff2 + d * DIM;
        const float* gfw = gate_ff_W + (size_t)d * 3 * DIM;

        tgemm_h16<3><<<gemm_grid(NN, 3 * INNER), 128, HSMEM_BYTES>>>(
            pxnh, wqkvh, pbqkv + d * 768, pqkvh, NN, 3 * INNER, DIM);

        cudaMemsetAsync(pden, 0, (size_t)NN * HEADS * sizeof(float), 0);
        cudaMemsetAsync(pagg, 0, (size_t)NN * INNER * sizeof(float), 0);
        cudaStreamWaitEvent(0, evL[d], 0);   // join: edge GEMM for this layer done
        attn_fused_k<<<warpBlocks_E, 256>>>(pqkvh, peL[d], src, dst, pden, pagg, EE);
        normalize_agg_k<<<(NN * INNER / 4 + 255) / 256, 256>>>(pagg, pden);

        tgemm_v4<<<gemm_grid(NN, DIM), 128, SMEM_BYTES>>>(pagg, wo, bod, py, NN, DIM, INNER);
        gated_ln_k<<<warpBlocks_N, 256>>>(py, px, gaw, l2g, l2b, px, pxnh, NN);

        tgemm_h16<1><<<gemm_grid(NN, FF), 128, HSMEM_BYTES>>>(
            pxnh, wf1h, bf1, pffh, NN, FF, DIM);
        tgemm_h16<0><<<gemm_grid(NN, DIM), 128, HSMEM_BYTES>>>(
            pffh, wf2h, bf2, py, NN, DIM, FF);

        if (d + 1 < DEPTH) {
            gated_ln_k<<<warpBlocks_N, 256>>>(py, px, gfw,
                                              ln1_g + (d + 1) * DIM, ln1_b + (d + 1) * DIM,
                                              px, pxnh, NN);
        } else {
            gated_residual_k<<<warpBlocks_N, 256>>>(py, px, gfw, px, NN);
        }
    }

    tgemm_v4<<<gemm_grid(NN, OUTD), 128, SMEM_BYTES>>>(px, pwt + WPROJ_OFF, bproj, out, NN, OUTD, DIM);
}